// round 1
// baseline (speedup 1.0000x reference)
#include <cuda_runtime.h>
#include <cstdint>

// LSTMPredictor: B=256, T=1024, H=128, 2-layer LSTM + linear head.
// Design: 32 clusters x 4 CTAs. Each cluster owns 8 batch rows; each CTA owns
// 32 hidden units (=> 128 gate rows per layer) with fp32 weights in SMEM.
// h1/h2 exchanged cluster-wide via DSMEM stores + cluster barriers.
// Inner product uses packed fma.rn.f32x2 (2 fp32 FMA / issue on sm_103a).

namespace {

constexpr int Bt = 256;
constexpr int Tt = 1024;
constexpr int Ht = 128;
constexpr int CL = 4;     // cluster size
constexpr int BC = 8;     // batches per cluster
constexpr int NTH = 256;  // threads per CTA
constexpr int WP = 132;   // weight row pitch (floats): 128 + 4 pad -> conflict-free LDS.128

// shared memory layout (floats)
constexpr int OFF_WH1 = 0;
constexpr int OFF_WI2 = OFF_WH1 + 128 * WP;
constexpr int OFF_WH2 = OFF_WI2 + 128 * WP;
constexpr int OFF_H1 = OFF_WH2 + 128 * WP;  // 2 parities x 128 x 8
constexpr int OFF_H2 = OFF_H1 + 2 * 128 * 8;
constexpr int OFF_G = OFF_H2 + 2 * 128 * 8;  // 128 x 8 gate scratch
constexpr int OFF_BS1 = OFF_G + 128 * 8;
constexpr int OFF_WX1 = OFF_BS1 + 128;
constexpr int OFF_BS2 = OFF_WX1 + 128;
constexpr int OFF_WO = OFF_BS2 + 128;
constexpr int OFF_X = OFF_WO + 128;        // 8
constexpr int OFF_BOUT = OFF_X + 8;        // 1 (+3 pad)
constexpr int SM_FLOATS = OFF_BOUT + 4;
constexpr int SM_BYTES = SM_FLOATS * 4;    // 225,328 B < 227 KB limit

typedef unsigned long long u64;

__device__ __forceinline__ u64 pk2(float a, float b) {
    u64 r;
    asm("mov.b64 %0, {%1,%2};" : "=l"(r) : "f"(a), "f"(b));
    return r;
}
__device__ __forceinline__ void fma2(u64& d, u64 a, u64 b) {
    asm("fma.rn.f32x2 %0, %1, %2, %3;" : "=l"(d) : "l"(a), "l"(b), "l"(d));
}
__device__ __forceinline__ float2 upk2(u64 v) {
    float2 f;
    asm("mov.b64 {%0,%1}, %2;" : "=f"(f.x), "=f"(f.y) : "l"(v));
    return f;
}
__device__ __forceinline__ uint32_t s2u(const void* p) {
    return (uint32_t)__cvta_generic_to_shared(p);
}
__device__ __forceinline__ void st_remote(uint32_t laddr, uint32_t peer, float v) {
    uint32_t r;
    asm("mapa.shared::cluster.u32 %0, %1, %2;" : "=r"(r) : "r"(laddr), "r"(peer));
    asm volatile("st.shared::cluster.f32 [%0], %1;" ::"r"(r), "f"(v) : "memory");
}
__device__ __forceinline__ void cluster_sync_i() {
    asm volatile("barrier.cluster.arrive.aligned;" ::: "memory");
    asm volatile("barrier.cluster.wait.aligned;" ::: "memory");
}
__device__ __forceinline__ float sigf(float x) {
    return 1.0f / (1.0f + __expf(-x));
}
__device__ __forceinline__ float tanh_fast(float x) {
    // tanh(x) = 2*sigma(2x) - 1 ; __expf has ~2^-21 rel err, fine for 1e-3 tol
    return 2.0f / (1.0f + __expf(-2.0f * x)) - 1.0f;
}

__global__ void __launch_bounds__(NTH, 1) lstm_cluster_kernel(
    const float* __restrict__ x, const float* __restrict__ Wih1,
    const float* __restrict__ Whh1, const float* __restrict__ bih1,
    const float* __restrict__ bhh1, const float* __restrict__ Wih2,
    const float* __restrict__ Whh2, const float* __restrict__ bih2,
    const float* __restrict__ bhh2, const float* __restrict__ Wout,
    const float* __restrict__ bout, float* __restrict__ out) {
    extern __shared__ float sm[];
    float* Wh1s = sm + OFF_WH1;
    float* Wi2s = sm + OFF_WI2;
    float* Wh2s = sm + OFF_WH2;
    float* h1b = sm + OFF_H1;
    float* h2b = sm + OFF_H2;
    float* gbuf = sm + OFF_G;
    float* bs1s = sm + OFF_BS1;
    float* wx1s = sm + OFF_WX1;
    float* bs2s = sm + OFF_BS2;
    float* wos = sm + OFF_WO;
    float* xS = sm + OFF_X;
    float* boS = sm + OFF_BOUT;

    const int tid = threadIdx.x;
    const int rank = blockIdx.x & 3;
    const int bbase = (blockIdx.x >> 2) * BC;
    const int U0 = rank * 32;

    // ---- load weights into SMEM (local gate rows: lr = gate*32 + unit) ----
    for (int idx = tid; idx < 128 * 32; idx += NTH) {  // float4 granules
        const int lr = idx >> 5;
        const int k4 = (idx & 31) << 2;
        const int grow = ((lr >> 5) * 128) + U0 + (lr & 31);
        *reinterpret_cast<float4*>(&Wh1s[lr * WP + k4]) =
            *reinterpret_cast<const float4*>(&Whh1[grow * Ht + k4]);
        *reinterpret_cast<float4*>(&Wi2s[lr * WP + k4]) =
            *reinterpret_cast<const float4*>(&Wih2[grow * Ht + k4]);
        *reinterpret_cast<float4*>(&Wh2s[lr * WP + k4]) =
            *reinterpret_cast<const float4*>(&Whh2[grow * Ht + k4]);
    }
    for (int lr = tid; lr < 128; lr += NTH) {
        const int grow = ((lr >> 5) * 128) + U0 + (lr & 31);
        bs1s[lr] = bih1[grow] + bhh1[grow];
        wx1s[lr] = Wih1[grow];
        bs2s[lr] = bih2[grow] + bhh2[grow];
        wos[lr] = Wout[lr];
    }
    for (int i = tid; i < 2 * 128 * 8; i += NTH) {
        h1b[i] = 0.0f;
        h2b[i] = 0.0f;
    }
    if (tid == 0) boS[0] = bout[0];
    __syncthreads();
    cluster_sync_i();  // peers' buffers zeroed before any remote stores

    // ---- per-thread fixed mappings ----
    const int lane = tid & 31;
    const int warp = tid >> 5;
    const int lr = warp * 16 + (lane & 15);  // gate row owned in GEMV stages
    const int half = lane >> 4;              // batch half: 0 -> b0..3, 1 -> b4..7
    const float* wrA = &Wh1s[lr * WP];
    const float* wrBi = &Wi2s[lr * WP];
    const float* wrBh = &Wh2s[lr * WP];
    const float bs1 = bs1s[lr];
    const float wx = wx1s[lr];
    const float bs2 = bs2s[lr];

    const int uu = tid >> 3;  // epilogue ownership: unit (0..31)
    const int bb = tid & 7;   // batch (0..7)
    const int hoff = (U0 + uu) * 8 + bb;
    const uint32_t h1u = s2u(h1b);
    const uint32_t h2u = s2u(h2b);
    const uint32_t p1 = (rank + 1) & 3, p2 = (rank + 2) & 3, p3 = (rank + 3) & 3;

    float c1 = 0.0f, c2 = 0.0f;
    float xreg = (tid < BC) ? x[(bbase + tid) * Tt + 0] : 0.0f;

    for (int t = 0; t < Tt; ++t) {
        const int p = t & 1;
        const float* h1prev = h1b + (p ^ 1) * 1024 + half * 4;
        const float* h2prev = h2b + (p ^ 1) * 1024 + half * 4;
        float* h1cur = h1b + p * 1024;
        const float* h1curr = h1cur + half * 4;
        float* h2cur = h2b + p * 1024;

        if (tid < BC) xS[tid] = xreg;
        __syncthreads();
        if (tid < BC && t + 1 < Tt) xreg = x[(bbase + tid) * Tt + (t + 1)];  // prefetch

        // ================= stage A: gates1 = Whh1 @ h1 + x*wih1 + b =================
        {
            const float4 xv = *reinterpret_cast<const float4*>(&xS[half * 4]);
            u64 a0 = pk2(bs1 + xv.x * wx, bs1 + xv.y * wx);
            u64 a1 = pk2(bs1 + xv.z * wx, bs1 + xv.w * wx);
#pragma unroll 8
            for (int k = 0; k < Ht; k += 4) {
                const float4 wv = *reinterpret_cast<const float4*>(&wrA[k]);
                const ulonglong2 h0 = *reinterpret_cast<const ulonglong2*>(&h1prev[(k + 0) * 8]);
                const ulonglong2 h1_ = *reinterpret_cast<const ulonglong2*>(&h1prev[(k + 1) * 8]);
                const ulonglong2 h2_ = *reinterpret_cast<const ulonglong2*>(&h1prev[(k + 2) * 8]);
                const ulonglong2 h3_ = *reinterpret_cast<const ulonglong2*>(&h1prev[(k + 3) * 8]);
                u64 w;
                w = pk2(wv.x, wv.x); fma2(a0, w, h0.x); fma2(a1, w, h0.y);
                w = pk2(wv.y, wv.y); fma2(a0, w, h1_.x); fma2(a1, w, h1_.y);
                w = pk2(wv.z, wv.z); fma2(a0, w, h2_.x); fma2(a1, w, h2_.y);
                w = pk2(wv.w, wv.w); fma2(a0, w, h3_.x); fma2(a1, w, h3_.y);
            }
            const float2 r0 = upk2(a0), r1 = upk2(a1);
            *reinterpret_cast<float4*>(&gbuf[lr * 8 + half * 4]) =
                make_float4(r0.x, r0.y, r1.x, r1.y);
        }
        __syncthreads();
        // ---- epilogue A: c1/h1 update, push h1 cluster-wide ----
        {
            const float gi = gbuf[uu * 8 + bb];
            const float gf = gbuf[(32 + uu) * 8 + bb];
            const float gg = gbuf[(64 + uu) * 8 + bb];
            const float go = gbuf[(96 + uu) * 8 + bb];
            c1 = sigf(gf) * c1 + sigf(gi) * tanh_fast(gg);
            const float h1v = sigf(go) * tanh_fast(c1);
            h1cur[hoff] = h1v;
            const uint32_t la = h1u + (uint32_t)(p * 1024 + hoff) * 4u;
            st_remote(la, p1, h1v);
            st_remote(la, p2, h1v);
            st_remote(la, p3, h1v);
        }
        cluster_sync_i();  // barrier #1: full h1(t) visible everywhere

        // ========== stage B: gates2 = Wih2 @ h1' + Whh2 @ h2 + b ==========
        {
            u64 a0 = pk2(bs2, bs2);
            u64 a1 = a0;
#pragma unroll 4
            for (int k = 0; k < Ht; k += 4) {
                const float4 wi = *reinterpret_cast<const float4*>(&wrBi[k]);
                const float4 wh = *reinterpret_cast<const float4*>(&wrBh[k]);
                const ulonglong2 x0 = *reinterpret_cast<const ulonglong2*>(&h1curr[(k + 0) * 8]);
                const ulonglong2 x1 = *reinterpret_cast<const ulonglong2*>(&h1curr[(k + 1) * 8]);
                const ulonglong2 x2 = *reinterpret_cast<const ulonglong2*>(&h1curr[(k + 2) * 8]);
                const ulonglong2 x3 = *reinterpret_cast<const ulonglong2*>(&h1curr[(k + 3) * 8]);
                const ulonglong2 y0 = *reinterpret_cast<const ulonglong2*>(&h2prev[(k + 0) * 8]);
                const ulonglong2 y1 = *reinterpret_cast<const ulonglong2*>(&h2prev[(k + 1) * 8]);
                const ulonglong2 y2 = *reinterpret_cast<const ulonglong2*>(&h2prev[(k + 2) * 8]);
                const ulonglong2 y3 = *reinterpret_cast<const ulonglong2*>(&h2prev[(k + 3) * 8]);
                u64 w;
                w = pk2(wi.x, wi.x); fma2(a0, w, x0.x); fma2(a1, w, x0.y);
                w = pk2(wh.x, wh.x); fma2(a0, w, y0.x); fma2(a1, w, y0.y);
                w = pk2(wi.y, wi.y); fma2(a0, w, x1.x); fma2(a1, w, x1.y);
                w = pk2(wh.y, wh.y); fma2(a0, w, y1.x); fma2(a1, w, y1.y);
                w = pk2(wi.z, wi.z); fma2(a0, w, x2.x); fma2(a1, w, x2.y);
                w = pk2(wh.z, wh.z); fma2(a0, w, y2.x); fma2(a1, w, y2.y);
                w = pk2(wi.w, wi.w); fma2(a0, w, x3.x); fma2(a1, w, x3.y);
                w = pk2(wh.w, wh.w); fma2(a0, w, y3.x); fma2(a1, w, y3.y);
            }
            const float2 r0 = upk2(a0), r1 = upk2(a1);
            *reinterpret_cast<float4*>(&gbuf[lr * 8 + half * 4]) =
                make_float4(r0.x, r0.y, r1.x, r1.y);
        }
        __syncthreads();
        // ---- epilogue B: c2/h2 update, push h2 cluster-wide ----
        {
            const float gi = gbuf[uu * 8 + bb];
            const float gf = gbuf[(32 + uu) * 8 + bb];
            const float gg = gbuf[(64 + uu) * 8 + bb];
            const float go = gbuf[(96 + uu) * 8 + bb];
            c2 = sigf(gf) * c2 + sigf(gi) * tanh_fast(gg);
            const float h2v = sigf(go) * tanh_fast(c2);
            h2cur[hoff] = h2v;
            const uint32_t la = h2u + (uint32_t)(p * 1024 + hoff) * 4u;
            st_remote(la, p1, h2v);
            st_remote(la, p2, h2v);
            st_remote(la, p3, h2v);
        }
        cluster_sync_i();  // barrier #2: full h2(t) visible everywhere

        // ---- output: each rank emits 2 batches: out[b,t] = wout . h2 + bout ----
        if (tid < 64) {
            const int w = tid >> 5;
            const int l = tid & 31;
            const int bl = rank * 2 + w;
            float s = 0.0f;
#pragma unroll
            for (int j = 0; j < 4; ++j) {
                const int k = l + 32 * j;
                s += h2cur[k * 8 + bl] * wos[k];
            }
            s += __shfl_xor_sync(0xffffffffu, s, 16);
            s += __shfl_xor_sync(0xffffffffu, s, 8);
            s += __shfl_xor_sync(0xffffffffu, s, 4);
            s += __shfl_xor_sync(0xffffffffu, s, 2);
            s += __shfl_xor_sync(0xffffffffu, s, 1);
            if (l == 0) out[(bbase + bl) * Tt + t] = s + boS[0];
        }
    }
}

}  // namespace

extern "C" void kernel_launch(void* const* d_in, const int* in_sizes, int n_in,
                              void* d_out, int out_size) {
    (void)in_sizes;
    (void)n_in;
    (void)out_size;
    const float* x = (const float*)d_in[0];
    const float* Wih1 = (const float*)d_in[1];
    const float* Whh1 = (const float*)d_in[2];
    const float* bih1 = (const float*)d_in[3];
    const float* bhh1 = (const float*)d_in[4];
    const float* Wih2 = (const float*)d_in[5];
    const float* Whh2 = (const float*)d_in[6];
    const float* bih2 = (const float*)d_in[7];
    const float* bhh2 = (const float*)d_in[8];
    const float* Wout = (const float*)d_in[9];
    const float* bout = (const float*)d_in[10];
    float* out = (float*)d_out;

    cudaFuncSetAttribute(lstm_cluster_kernel,
                         cudaFuncAttributeMaxDynamicSharedMemorySize, SM_BYTES);

    cudaLaunchConfig_t cfg = {};
    cfg.gridDim = dim3((Bt / BC) * CL, 1, 1);  // 128 CTAs = 32 clusters of 4
    cfg.blockDim = dim3(NTH, 1, 1);
    cfg.dynamicSmemBytes = SM_BYTES;
    cfg.stream = 0;
    cudaLaunchAttribute attrs[1];
    attrs[0].id = cudaLaunchAttributeClusterDimension;
    attrs[0].val.clusterDim.x = CL;
    attrs[0].val.clusterDim.y = 1;
    attrs[0].val.clusterDim.z = 1;
    cfg.attrs = attrs;
    cfg.numAttrs = 1;

    cudaLaunchKernelEx(&cfg, lstm_cluster_kernel, x, Wih1, Whh1, bih1, bhh1,
                       Wih2, Whh2, bih2, bhh2, Wout, bout, out);
}

// round 2
// speedup vs baseline: 1.0000x; 1.0000x over previous
#include <cuda_runtime.h>
#include <cstdint>

// LSTMPredictor: B=256, T=1024, H=128, 2-layer LSTM + linear head.
// Design: 32 clusters x 4 CTAs. Each cluster owns 8 batch rows; each CTA owns
// 32 hidden units (=> 128 gate rows per layer) with fp32 weights in SMEM.
// h1/h2 exchanged cluster-wide via DSMEM stores + cluster barriers.
// Inner product uses packed fma.rn.f32x2 (2 fp32 FMA / issue on sm_103a).

namespace {

constexpr int Bt = 256;
constexpr int Tt = 1024;
constexpr int Ht = 128;
constexpr int CL = 4;     // cluster size
constexpr int BC = 8;     // batches per cluster
constexpr int NTH = 256;  // threads per CTA
constexpr int WP = 132;   // weight row pitch (floats): 128 + 4 pad -> conflict-free LDS.128

// shared memory layout (floats)
constexpr int OFF_WH1 = 0;
constexpr int OFF_WI2 = OFF_WH1 + 128 * WP;
constexpr int OFF_WH2 = OFF_WI2 + 128 * WP;
constexpr int OFF_H1 = OFF_WH2 + 128 * WP;  // 2 parities x 128 x 8
constexpr int OFF_H2 = OFF_H1 + 2 * 128 * 8;
constexpr int OFF_G = OFF_H2 + 2 * 128 * 8;  // 128 x 8 gate scratch
constexpr int OFF_BS1 = OFF_G + 128 * 8;
constexpr int OFF_WX1 = OFF_BS1 + 128;
constexpr int OFF_BS2 = OFF_WX1 + 128;
constexpr int OFF_WO = OFF_BS2 + 128;
constexpr int OFF_X = OFF_WO + 128;        // 8
constexpr int OFF_BOUT = OFF_X + 8;        // 1 (+3 pad)
constexpr int SM_FLOATS = OFF_BOUT + 4;
constexpr int SM_BYTES = SM_FLOATS * 4;    // 225,328 B < 227 KB limit

typedef unsigned long long u64;

__device__ __forceinline__ u64 pk2(float a, float b) {
    u64 r;
    asm("mov.b64 %0, {%1,%2};" : "=l"(r) : "f"(a), "f"(b));
    return r;
}
__device__ __forceinline__ void fma2(u64& d, u64 a, u64 b) {
    asm("fma.rn.f32x2 %0, %1, %2, %3;" : "=l"(d) : "l"(a), "l"(b), "l"(d));
}
__device__ __forceinline__ float2 upk2(u64 v) {
    float2 f;
    asm("mov.b64 {%0,%1}, %2;" : "=f"(f.x), "=f"(f.y) : "l"(v));
    return f;
}
__device__ __forceinline__ uint32_t s2u(const void* p) {
    return (uint32_t)__cvta_generic_to_shared(p);
}
__device__ __forceinline__ void st_remote(uint32_t laddr, uint32_t peer, float v) {
    uint32_t r;
    asm("mapa.shared::cluster.u32 %0, %1, %2;" : "=r"(r) : "r"(laddr), "r"(peer));
    asm volatile("st.shared::cluster.f32 [%0], %1;" ::"r"(r), "f"(v) : "memory");
}
__device__ __forceinline__ void cluster_sync_i() {
    asm volatile("barrier.cluster.arrive.aligned;" ::: "memory");
    asm volatile("barrier.cluster.wait.aligned;" ::: "memory");
}
__device__ __forceinline__ float sigf(float x) {
    return 1.0f / (1.0f + __expf(-x));
}
__device__ __forceinline__ float tanh_fast(float x) {
    // tanh(x) = 2*sigma(2x) - 1 ; __expf has ~2^-21 rel err, fine for 1e-3 tol
    return 2.0f / (1.0f + __expf(-2.0f * x)) - 1.0f;
}

__global__ void __launch_bounds__(NTH, 1) lstm_cluster_kernel(
    const float* __restrict__ x, const float* __restrict__ Wih1,
    const float* __restrict__ Whh1, const float* __restrict__ bih1,
    const float* __restrict__ bhh1, const float* __restrict__ Wih2,
    const float* __restrict__ Whh2, const float* __restrict__ bih2,
    const float* __restrict__ bhh2, const float* __restrict__ Wout,
    const float* __restrict__ bout, float* __restrict__ out) {
    extern __shared__ float sm[];
    float* Wh1s = sm + OFF_WH1;
    float* Wi2s = sm + OFF_WI2;
    float* Wh2s = sm + OFF_WH2;
    float* h1b = sm + OFF_H1;
    float* h2b = sm + OFF_H2;
    float* gbuf = sm + OFF_G;
    float* bs1s = sm + OFF_BS1;
    float* wx1s = sm + OFF_WX1;
    float* bs2s = sm + OFF_BS2;
    float* wos = sm + OFF_WO;
    float* xS = sm + OFF_X;
    float* boS = sm + OFF_BOUT;

    const int tid = threadIdx.x;
    const int rank = blockIdx.x & 3;
    const int bbase = (blockIdx.x >> 2) * BC;
    const int U0 = rank * 32;

    // ---- load weights into SMEM (local gate rows: lr = gate*32 + unit) ----
    for (int idx = tid; idx < 128 * 32; idx += NTH) {  // float4 granules
        const int lr = idx >> 5;
        const int k4 = (idx & 31) << 2;
        const int grow = ((lr >> 5) * 128) + U0 + (lr & 31);
        *reinterpret_cast<float4*>(&Wh1s[lr * WP + k4]) =
            *reinterpret_cast<const float4*>(&Whh1[grow * Ht + k4]);
        *reinterpret_cast<float4*>(&Wi2s[lr * WP + k4]) =
            *reinterpret_cast<const float4*>(&Wih2[grow * Ht + k4]);
        *reinterpret_cast<float4*>(&Wh2s[lr * WP + k4]) =
            *reinterpret_cast<const float4*>(&Whh2[grow * Ht + k4]);
    }
    for (int lr = tid; lr < 128; lr += NTH) {
        const int grow = ((lr >> 5) * 128) + U0 + (lr & 31);
        bs1s[lr] = bih1[grow] + bhh1[grow];
        wx1s[lr] = Wih1[grow];
        bs2s[lr] = bih2[grow] + bhh2[grow];
        wos[lr] = Wout[lr];
    }
    for (int i = tid; i < 2 * 128 * 8; i += NTH) {
        h1b[i] = 0.0f;
        h2b[i] = 0.0f;
    }
    if (tid == 0) boS[0] = bout[0];
    __syncthreads();
    cluster_sync_i();  // peers' buffers zeroed before any remote stores

    // ---- per-thread fixed mappings ----
    const int lane = tid & 31;
    const int warp = tid >> 5;
    const int lr = warp * 16 + (lane & 15);  // gate row owned in GEMV stages
    const int half = lane >> 4;              // batch half: 0 -> b0..3, 1 -> b4..7
    const float* wrA = &Wh1s[lr * WP];
    const float* wrBi = &Wi2s[lr * WP];
    const float* wrBh = &Wh2s[lr * WP];
    const float bs1 = bs1s[lr];
    const float wx = wx1s[lr];
    const float bs2 = bs2s[lr];

    const int uu = tid >> 3;  // epilogue ownership: unit (0..31)
    const int bb = tid & 7;   // batch (0..7)
    const int hoff = (U0 + uu) * 8 + bb;
    const uint32_t h1u = s2u(h1b);
    const uint32_t h2u = s2u(h2b);
    const uint32_t p1 = (rank + 1) & 3, p2 = (rank + 2) & 3, p3 = (rank + 3) & 3;

    float c1 = 0.0f, c2 = 0.0f;
    float xreg = (tid < BC) ? x[(bbase + tid) * Tt + 0] : 0.0f;

    for (int t = 0; t < Tt; ++t) {
        const int p = t & 1;
        const float* h1prev = h1b + (p ^ 1) * 1024 + half * 4;
        const float* h2prev = h2b + (p ^ 1) * 1024 + half * 4;
        float* h1cur = h1b + p * 1024;
        const float* h1curr = h1cur + half * 4;
        float* h2cur = h2b + p * 1024;

        if (tid < BC) xS[tid] = xreg;
        __syncthreads();
        if (tid < BC && t + 1 < Tt) xreg = x[(bbase + tid) * Tt + (t + 1)];  // prefetch

        // ================= stage A: gates1 = Whh1 @ h1 + x*wih1 + b =================
        {
            const float4 xv = *reinterpret_cast<const float4*>(&xS[half * 4]);
            u64 a0 = pk2(bs1 + xv.x * wx, bs1 + xv.y * wx);
            u64 a1 = pk2(bs1 + xv.z * wx, bs1 + xv.w * wx);
#pragma unroll 8
            for (int k = 0; k < Ht; k += 4) {
                const float4 wv = *reinterpret_cast<const float4*>(&wrA[k]);
                const ulonglong2 h0 = *reinterpret_cast<const ulonglong2*>(&h1prev[(k + 0) * 8]);
                const ulonglong2 h1_ = *reinterpret_cast<const ulonglong2*>(&h1prev[(k + 1) * 8]);
                const ulonglong2 h2_ = *reinterpret_cast<const ulonglong2*>(&h1prev[(k + 2) * 8]);
                const ulonglong2 h3_ = *reinterpret_cast<const ulonglong2*>(&h1prev[(k + 3) * 8]);
                u64 w;
                w = pk2(wv.x, wv.x); fma2(a0, w, h0.x); fma2(a1, w, h0.y);
                w = pk2(wv.y, wv.y); fma2(a0, w, h1_.x); fma2(a1, w, h1_.y);
                w = pk2(wv.z, wv.z); fma2(a0, w, h2_.x); fma2(a1, w, h2_.y);
                w = pk2(wv.w, wv.w); fma2(a0, w, h3_.x); fma2(a1, w, h3_.y);
            }
            const float2 r0 = upk2(a0), r1 = upk2(a1);
            *reinterpret_cast<float4*>(&gbuf[lr * 8 + half * 4]) =
                make_float4(r0.x, r0.y, r1.x, r1.y);
        }
        __syncthreads();
        // ---- epilogue A: c1/h1 update, push h1 cluster-wide ----
        {
            const float gi = gbuf[uu * 8 + bb];
            const float gf = gbuf[(32 + uu) * 8 + bb];
            const float gg = gbuf[(64 + uu) * 8 + bb];
            const float go = gbuf[(96 + uu) * 8 + bb];
            c1 = sigf(gf) * c1 + sigf(gi) * tanh_fast(gg);
            const float h1v = sigf(go) * tanh_fast(c1);
            h1cur[hoff] = h1v;
            const uint32_t la = h1u + (uint32_t)(p * 1024 + hoff) * 4u;
            st_remote(la, p1, h1v);
            st_remote(la, p2, h1v);
            st_remote(la, p3, h1v);
        }
        cluster_sync_i();  // barrier #1: full h1(t) visible everywhere

        // ========== stage B: gates2 = Wih2 @ h1' + Whh2 @ h2 + b ==========
        {
            u64 a0 = pk2(bs2, bs2);
            u64 a1 = a0;
#pragma unroll 4
            for (int k = 0; k < Ht; k += 4) {
                const float4 wi = *reinterpret_cast<const float4*>(&wrBi[k]);
                const float4 wh = *reinterpret_cast<const float4*>(&wrBh[k]);
                const ulonglong2 x0 = *reinterpret_cast<const ulonglong2*>(&h1curr[(k + 0) * 8]);
                const ulonglong2 x1 = *reinterpret_cast<const ulonglong2*>(&h1curr[(k + 1) * 8]);
                const ulonglong2 x2 = *reinterpret_cast<const ulonglong2*>(&h1curr[(k + 2) * 8]);
                const ulonglong2 x3 = *reinterpret_cast<const ulonglong2*>(&h1curr[(k + 3) * 8]);
                const ulonglong2 y0 = *reinterpret_cast<const ulonglong2*>(&h2prev[(k + 0) * 8]);
                const ulonglong2 y1 = *reinterpret_cast<const ulonglong2*>(&h2prev[(k + 1) * 8]);
                const ulonglong2 y2 = *reinterpret_cast<const ulonglong2*>(&h2prev[(k + 2) * 8]);
                const ulonglong2 y3 = *reinterpret_cast<const ulonglong2*>(&h2prev[(k + 3) * 8]);
                u64 w;
                w = pk2(wi.x, wi.x); fma2(a0, w, x0.x); fma2(a1, w, x0.y);
                w = pk2(wh.x, wh.x); fma2(a0, w, y0.x); fma2(a1, w, y0.y);
                w = pk2(wi.y, wi.y); fma2(a0, w, x1.x); fma2(a1, w, x1.y);
                w = pk2(wh.y, wh.y); fma2(a0, w, y1.x); fma2(a1, w, y1.y);
                w = pk2(wi.z, wi.z); fma2(a0, w, x2.x); fma2(a1, w, x2.y);
                w = pk2(wh.z, wh.z); fma2(a0, w, y2.x); fma2(a1, w, y2.y);
                w = pk2(wi.w, wi.w); fma2(a0, w, x3.x); fma2(a1, w, x3.y);
                w = pk2(wh.w, wh.w); fma2(a0, w, y3.x); fma2(a1, w, y3.y);
            }
            const float2 r0 = upk2(a0), r1 = upk2(a1);
            *reinterpret_cast<float4*>(&gbuf[lr * 8 + half * 4]) =
                make_float4(r0.x, r0.y, r1.x, r1.y);
        }
        __syncthreads();
        // ---- epilogue B: c2/h2 update, push h2 cluster-wide ----
        {
            const float gi = gbuf[uu * 8 + bb];
            const float gf = gbuf[(32 + uu) * 8 + bb];
            const float gg = gbuf[(64 + uu) * 8 + bb];
            const float go = gbuf[(96 + uu) * 8 + bb];
            c2 = sigf(gf) * c2 + sigf(gi) * tanh_fast(gg);
            const float h2v = sigf(go) * tanh_fast(c2);
            h2cur[hoff] = h2v;
            const uint32_t la = h2u + (uint32_t)(p * 1024 + hoff) * 4u;
            st_remote(la, p1, h2v);
            st_remote(la, p2, h2v);
            st_remote(la, p3, h2v);
        }
        cluster_sync_i();  // barrier #2: full h2(t) visible everywhere

        // ---- output: each rank emits 2 batches: out[b,t] = wout . h2 + bout ----
        if (tid < 64) {
            const int w = tid >> 5;
            const int l = tid & 31;
            const int bl = rank * 2 + w;
            float s = 0.0f;
#pragma unroll
            for (int j = 0; j < 4; ++j) {
                const int k = l + 32 * j;
                s += h2cur[k * 8 + bl] * wos[k];
            }
            s += __shfl_xor_sync(0xffffffffu, s, 16);
            s += __shfl_xor_sync(0xffffffffu, s, 8);
            s += __shfl_xor_sync(0xffffffffu, s, 4);
            s += __shfl_xor_sync(0xffffffffu, s, 2);
            s += __shfl_xor_sync(0xffffffffu, s, 1);
            if (l == 0) out[(bbase + bl) * Tt + t] = s + boS[0];
        }
    }
}

}  // namespace

extern "C" void kernel_launch(void* const* d_in, const int* in_sizes, int n_in,
                              void* d_out, int out_size) {
    (void)in_sizes;
    (void)n_in;
    (void)out_size;
    const float* x = (const float*)d_in[0];
    const float* Wih1 = (const float*)d_in[1];
    const float* Whh1 = (const float*)d_in[2];
    const float* bih1 = (const float*)d_in[3];
    const float* bhh1 = (const float*)d_in[4];
    const float* Wih2 = (const float*)d_in[5];
    const float* Whh2 = (const float*)d_in[6];
    const float* bih2 = (const float*)d_in[7];
    const float* bhh2 = (const float*)d_in[8];
    const float* Wout = (const float*)d_in[9];
    const float* bout = (const float*)d_in[10];
    float* out = (float*)d_out;

    cudaFuncSetAttribute(lstm_cluster_kernel,
                         cudaFuncAttributeMaxDynamicSharedMemorySize, SM_BYTES);

    cudaLaunchConfig_t cfg = {};
    cfg.gridDim = dim3((Bt / BC) * CL, 1, 1);  // 128 CTAs = 32 clusters of 4
    cfg.blockDim = dim3(NTH, 1, 1);
    cfg.dynamicSmemBytes = SM_BYTES;
    cfg.stream = 0;
    cudaLaunchAttribute attrs[1];
    attrs[0].id = cudaLaunchAttributeClusterDimension;
    attrs[0].val.clusterDim.x = CL;
    attrs[0].val.clusterDim.y = 1;
    attrs[0].val.clusterDim.z = 1;
    cfg.attrs = attrs;
    cfg.numAttrs = 1;

    cudaLaunchKernelEx(&cfg, lstm_cluster_kernel, x, Wih1, Whh1, bih1, bhh1,
                       Wih2, Whh2, bih2, bhh2, Wout, bout, out);
}

// round 4
// speedup vs baseline: 1.4258x; 1.4258x over previous
#include <cuda_runtime.h>
#include <cstdint>

// LSTMPredictor: B=256, T=1024, H=128, 2-layer LSTM + linear head.
// 32 clusters x 4 CTAs. Each CTA owns 32 hidden units per layer (128 gate rows),
// fp32 weights in SMEM stored kp-major pair-interleaved for packed fma.rn.f32x2.
// Per thread: 2 rows x 8 batches x 32 k (k-split 4). h stored [batch][k].
// Split cluster barriers overlapped with independent GEMV work.
// R3 fix: h loads in gemv now include the per-warp k-split offset (ks*32).

namespace {

constexpr int Bt = 256;
constexpr int Tt = 1024;
constexpr int Ht = 128;
constexpr int CL = 4;
constexpr int BC = 8;
constexpr int NTH = 256;

// smem offsets (floats)
constexpr int OFF_W1  = 0;          // Whh1 pair-interleaved: 64kp*64rq*4 = 16384
constexpr int OFF_W2H = 16384;      // Whh2
constexpr int OFF_W2I = 32768;      // Wih2
constexpr int OFF_H1  = 49152;      // 2 parity * 8 b * 128 k = 2048
constexpr int OFF_H2  = 51200;      // 2048
constexpr int OFF_G   = 53248;      // gbuf partials: 4j*4ks*64rq*4 = 4096
constexpr int OFF_BS1 = 57344;      // 128
constexpr int OFF_WX  = 57472;      // 128
constexpr int OFF_BS2 = 57600;      // 128
constexpr int OFF_WO  = 57728;      // 128
constexpr int OFF_X   = 57856;      // 2*8
constexpr int OFF_BO  = 57872;      // 1 (+pad)
constexpr int SM_FLOATS = 57876;
constexpr int SM_BYTES = SM_FLOATS * 4;

typedef unsigned long long u64;

__device__ __forceinline__ u64 pk2(float a, float b) {
    u64 r;
    asm("mov.b64 %0, {%1,%2};" : "=l"(r) : "f"(a), "f"(b));
    return r;
}
__device__ __forceinline__ void fma2(u64& d, u64 a, u64 b) {
    asm("fma.rn.f32x2 %0, %1, %2, %3;" : "=l"(d) : "l"(a), "l"(b), "l"(d));
}
__device__ __forceinline__ float2 upk2(u64 v) {
    float2 f;
    asm("mov.b64 {%0,%1}, %2;" : "=f"(f.x), "=f"(f.y) : "l"(v));
    return f;
}
__device__ __forceinline__ uint32_t s2u(const void* p) {
    return (uint32_t)__cvta_generic_to_shared(p);
}
__device__ __forceinline__ void st_remote(uint32_t laddr, uint32_t peer, float v) {
    uint32_t r;
    asm("mapa.shared::cluster.u32 %0, %1, %2;" : "=r"(r) : "r"(laddr), "r"(peer));
    asm volatile("st.shared::cluster.f32 [%0], %1;" ::"r"(r), "f"(v) : "memory");
}
__device__ __forceinline__ void cl_arrive() {
    asm volatile("barrier.cluster.arrive.aligned;" ::: "memory");
}
__device__ __forceinline__ void cl_wait() {
    asm volatile("barrier.cluster.wait.aligned;" ::: "memory");
}
__device__ __forceinline__ float sigf(float x) {
    return 1.0f / (1.0f + __expf(-x));
}
__device__ __forceinline__ float tanh_fast(float x) {
    return 2.0f / (1.0f + __expf(-2.0f * x)) - 1.0f;
}

__global__ void __launch_bounds__(NTH, 1) lstm_cluster_kernel(
    const float* __restrict__ x, const float* __restrict__ Wih1,
    const float* __restrict__ Whh1, const float* __restrict__ bih1,
    const float* __restrict__ bhh1, const float* __restrict__ Wih2,
    const float* __restrict__ Whh2, const float* __restrict__ bih2,
    const float* __restrict__ bhh2, const float* __restrict__ Wout,
    const float* __restrict__ bout, float* __restrict__ out) {
    extern __shared__ float sm[];
    float* W1s = sm + OFF_W1;
    float* W2hs = sm + OFF_W2H;
    float* W2is = sm + OFF_W2I;
    float* h1b = sm + OFF_H1;
    float* h2b = sm + OFF_H2;
    float* gb = sm + OFF_G;
    float* bs1s = sm + OFF_BS1;
    float* wxs = sm + OFF_WX;
    float* bs2s = sm + OFF_BS2;
    float* wos = sm + OFF_WO;
    float* xS = sm + OFF_X;
    float* boS = sm + OFF_BO;

    const int tid = threadIdx.x;
    const int lane = tid & 31;
    const int warp = tid >> 5;
    const int rank = blockIdx.x & 3;
    const int bbase = (blockIdx.x >> 2) * BC;
    const int U0 = rank * 32;

    // ---- weight load: pair-interleaved kp-major ----
    // dst float4 at [kp*256 + rq*4] = { w[2rq][2kp], w[2rq][2kp+1], w[2rq+1][2kp], w[2rq+1][2kp+1] }
    for (int idx = tid; idx < 64 * 64; idx += NTH) {
        const int kp = idx >> 6;
        const int rq = idx & 63;
        const int k0 = kp * 2;
        const int lr0 = rq * 2, lr1 = lr0 + 1;
        const int g0 = ((lr0 >> 5) << 7) + U0 + (lr0 & 31);
        const int g1 = ((lr1 >> 5) << 7) + U0 + (lr1 & 31);
        const int d = kp * 256 + rq * 4;
        {
            float2 a = *reinterpret_cast<const float2*>(&Whh1[g0 * Ht + k0]);
            float2 b = *reinterpret_cast<const float2*>(&Whh1[g1 * Ht + k0]);
            *reinterpret_cast<float4*>(&W1s[d]) = make_float4(a.x, a.y, b.x, b.y);
        }
        {
            float2 a = *reinterpret_cast<const float2*>(&Whh2[g0 * Ht + k0]);
            float2 b = *reinterpret_cast<const float2*>(&Whh2[g1 * Ht + k0]);
            *reinterpret_cast<float4*>(&W2hs[d]) = make_float4(a.x, a.y, b.x, b.y);
        }
        {
            float2 a = *reinterpret_cast<const float2*>(&Wih2[g0 * Ht + k0]);
            float2 b = *reinterpret_cast<const float2*>(&Wih2[g1 * Ht + k0]);
            *reinterpret_cast<float4*>(&W2is[d]) = make_float4(a.x, a.y, b.x, b.y);
        }
    }
    for (int lr = tid; lr < 128; lr += NTH) {
        const int grow = ((lr >> 5) << 7) + U0 + (lr & 31);
        bs1s[lr] = bih1[grow] + bhh1[grow];
        wxs[lr] = Wih1[grow];
        bs2s[lr] = bih2[grow] + bhh2[grow];
        wos[lr] = Wout[lr];
    }
    for (int i = tid; i < 2048; i += NTH) {
        h1b[i] = 0.0f;
        h2b[i] = 0.0f;
    }
    if (tid < BC) xS[tid] = x[(bbase + tid) * Tt + 0];
    if (tid == 0) boS[0] = bout[0];
    __syncthreads();
    cl_arrive();
    cl_wait();  // peers zeroed before any remote stores

    // ---- compute-phase mapping: ks = warp>>1 (k-split of 4x32), rq = 0..63 ----
    const int ks = warp >> 1;
    const int koff = ks * 32;  // this warp's k-range base within h vectors
    const int rq = ((warp & 1) << 5) | lane;
    const float* wA = W1s + ks * 16 * 256 + rq * 4;
    const float* wBh = W2hs + ks * 16 * 256 + rq * 4;
    const float* wBi = W2is + ks * 16 * 256 + rq * 4;
    const float bs1_0 = bs1s[2 * rq], bs1_1 = bs1s[2 * rq + 1];
    const float wx0 = wxs[2 * rq], wx1 = wxs[2 * rq + 1];
    const float bs2_0 = bs2s[2 * rq], bs2_1 = bs2s[2 * rq + 1];
    const float boutr = boS[0];

    // epilogue mapping: unit uu = tid&31, batch bb = tid>>5
    const int uu = tid & 31;
    const int bb = tid >> 5;
    const int hoff = bb * 128 + U0 + uu;  // within a parity bank
    const uint32_t h1u = s2u(h1b);
    const uint32_t h2u = s2u(h2b);
    const uint32_t p1 = (rank + 1) & 3, p2r = (rank + 2) & 3, p3 = (rank + 3) & 3;
    // gbuf gather indices for the 4 gates (this thread's unit/batch)
    int goff[4];
#pragma unroll
    for (int g = 0; g < 4; ++g) {
        const int lr = g * 32 + uu;
        const int rqg = lr >> 1;
        const int s = lr & 1;
        const int j = s * 2 + (bb >> 2);
        goff[g] = ((j * 4) * 64 + rqg) * 4 + (bb & 3);  // +ks*256 per partial
    }

    float c1 = 0.0f, c2 = 0.0f;
    float xreg = (tid < BC && Tt > 1) ? x[(bbase + tid) * Tt + 1] : 0.0f;

    // GEMV: acc[0..7] = row r0 batches 0..7 (k-paired), acc[8..15] = row r1.
    auto gemv = [&](u64* acc, const float* wp, const float* hp) {
#pragma unroll
        for (int it = 0; it < 8; ++it) {
            const ulonglong2 wqa =
                *reinterpret_cast<const ulonglong2*>(wp + it * 512);
            const ulonglong2 wqb =
                *reinterpret_cast<const ulonglong2*>(wp + it * 512 + 256);
#pragma unroll
            for (int b = 0; b < 8; ++b) {
                const ulonglong2 hv = *reinterpret_cast<const ulonglong2*>(
                    hp + b * 128 + koff + it * 4);
                fma2(acc[b], wqa.x, hv.x);
                fma2(acc[8 + b], wqa.y, hv.x);
                fma2(acc[b], wqb.x, hv.y);
                fma2(acc[8 + b], wqb.y, hv.y);
            }
        }
    };
    auto redstore = [&](u64* acc) {
#pragma unroll
        for (int s = 0; s < 2; ++s)
#pragma unroll
            for (int bq = 0; bq < 2; ++bq) {
                float2 t0 = upk2(acc[s * 8 + bq * 4 + 0]);
                float2 t1 = upk2(acc[s * 8 + bq * 4 + 1]);
                float2 t2 = upk2(acc[s * 8 + bq * 4 + 2]);
                float2 t3 = upk2(acc[s * 8 + bq * 4 + 3]);
                const int j = s * 2 + bq;
                reinterpret_cast<float4*>(gb)[(j * 4 + ks) * 64 + rq] =
                    make_float4(t0.x + t0.y, t1.x + t1.y, t2.x + t2.y,
                                t3.x + t3.y);
            }
    };
    auto gather = [&](int g) -> float {
        const float* base = gb + goff[g];
        return base[0] + base[256] + base[512] + base[768];
    };

    for (int t = 0; t < Tt; ++t) {
        const int p = t & 1;
        const float* h1prev = h1b + (p ^ 1) * 1024;
        const float* h2prev = h2b + (p ^ 1) * 1024;
        float* h1cur = h1b + p * 1024;
        float* h2cur = h2b + p * 1024;

        // ===== stage A: gates1 = Whh1 @ h1(t-1) + x*wih1 + b (partials) =====
        {
            u64 A[16];
            if (ks == 0) {
                const float* xp = xS + p * 8;
#pragma unroll
                for (int b = 0; b < 8; ++b) {
                    const float xb = xp[b];
                    A[b] = pk2(bs1_0 + xb * wx0, 0.0f);
                    A[8 + b] = pk2(bs1_1 + xb * wx1, 0.0f);
                }
            } else {
#pragma unroll
                for (int i = 0; i < 16; ++i) A[i] = 0ull;
            }
            gemv(A, wA, h1prev);
            redstore(A);
        }

        // barrier2(t-1) hidden behind stage A; then output(t-1)
        if (t > 0) {
            cl_wait();
            if (tid < 64) {
                const int ow = tid >> 5;
                const int bl = rank * 2 + ow;
                const float4 hv = *reinterpret_cast<const float4*>(
                    h2prev + bl * 128 + lane * 4);
                const float4 wv =
                    *reinterpret_cast<const float4*>(wos + lane * 4);
                float s = hv.x * wv.x + hv.y * wv.y + hv.z * wv.z + hv.w * wv.w;
                s += __shfl_xor_sync(0xffffffffu, s, 16);
                s += __shfl_xor_sync(0xffffffffu, s, 8);
                s += __shfl_xor_sync(0xffffffffu, s, 4);
                s += __shfl_xor_sync(0xffffffffu, s, 2);
                s += __shfl_xor_sync(0xffffffffu, s, 1);
                if (lane == 0) out[(bbase + bl) * Tt + (t - 1)] = s + boutr;
            }
        }
        __syncthreads();

        // ===== epilogue A: c1/h1 update + cluster push =====
        {
            const float gi = gather(0);
            const float gf = gather(1);
            const float gg = gather(2);
            const float go = gather(3);
            c1 = sigf(gf) * c1 + sigf(gi) * tanh_fast(gg);
            const float h1v = sigf(go) * tanh_fast(c1);
            h1cur[hoff] = h1v;
            const uint32_t la = h1u + (uint32_t)(p * 1024 + hoff) * 4u;
            st_remote(la, p1, h1v);
            st_remote(la, p2r, h1v);
            st_remote(la, p3, h1v);
        }
        if (tid < BC) {
            xS[(p ^ 1) * 8 + tid] = xreg;
            if (t + 2 < Tt) xreg = x[(bbase + tid) * Tt + (t + 2)];
        }
        cl_arrive();  // barrier1: h1(t) in flight

        // ===== stage B part 1 (overlaps barrier1): Whh2 @ h2(t-1) + b =====
        u64 Bk[16];
        if (ks == 0) {
#pragma unroll
            for (int b = 0; b < 8; ++b) {
                Bk[b] = pk2(bs2_0, 0.0f);
                Bk[8 + b] = pk2(bs2_1, 0.0f);
            }
        } else {
#pragma unroll
            for (int i = 0; i < 16; ++i) Bk[i] = 0ull;
        }
        gemv(Bk, wBh, h2prev);
        cl_wait();  // barrier1: full h1(t) visible

        // ===== stage B part 2: += Wih2 @ h1(t) =====
        gemv(Bk, wBi, h1cur);
        redstore(Bk);
        __syncthreads();

        // ===== epilogue B: c2/h2 update + cluster push =====
        {
            const float gi = gather(0);
            const float gf = gather(1);
            const float gg = gather(2);
            const float go = gather(3);
            c2 = sigf(gf) * c2 + sigf(gi) * tanh_fast(gg);
            const float h2v = sigf(go) * tanh_fast(c2);
            h2cur[hoff] = h2v;
            const uint32_t la = h2u + (uint32_t)(p * 1024 + hoff) * 4u;
            st_remote(la, p1, h2v);
            st_remote(la, p2r, h2v);
            st_remote(la, p3, h2v);
        }
        __syncthreads();  // protect gbuf: epiB reads done before next stage A writes
        cl_arrive();      // barrier2: h2(t) in flight (hidden behind next stage A)
    }

    // drain: last output
    cl_wait();
    if (tid < 64) {
        const int ow = tid >> 5;
        const int bl = rank * 2 + ow;
        const float* h2last = h2b + ((Tt - 1) & 1) * 1024;
        const float4 hv =
            *reinterpret_cast<const float4*>(h2last + bl * 128 + lane * 4);
        const float4 wv = *reinterpret_cast<const float4*>(wos + lane * 4);
        float s = hv.x * wv.x + hv.y * wv.y + hv.z * wv.z + hv.w * wv.w;
        s += __shfl_xor_sync(0xffffffffu, s, 16);
        s += __shfl_xor_sync(0xffffffffu, s, 8);
        s += __shfl_xor_sync(0xffffffffu, s, 4);
        s += __shfl_xor_sync(0xffffffffu, s, 2);
        s += __shfl_xor_sync(0xffffffffu, s, 1);
        if (lane == 0) out[(bbase + bl) * Tt + (Tt - 1)] = s + boutr;
    }
}

}  // namespace

extern "C" void kernel_launch(void* const* d_in, const int* in_sizes, int n_in,
                              void* d_out, int out_size) {
    (void)in_sizes;
    (void)n_in;
    (void)out_size;
    const float* x = (const float*)d_in[0];
    const float* Wih1 = (const float*)d_in[1];
    const float* Whh1 = (const float*)d_in[2];
    const float* bih1 = (const float*)d_in[3];
    const float* bhh1 = (const float*)d_in[4];
    const float* Wih2 = (const float*)d_in[5];
    const float* Whh2 = (const float*)d_in[6];
    const float* bih2 = (const float*)d_in[7];
    const float* bhh2 = (const float*)d_in[8];
    const float* Wout = (const float*)d_in[9];
    const float* bout = (const float*)d_in[10];
    float* out = (float*)d_out;

    cudaFuncSetAttribute(lstm_cluster_kernel,
                         cudaFuncAttributeMaxDynamicSharedMemorySize, SM_BYTES);

    cudaLaunchConfig_t cfg = {};
    cfg.gridDim = dim3((Bt / BC) * CL, 1, 1);  // 128 CTAs = 32 clusters of 4
    cfg.blockDim = dim3(NTH, 1, 1);
    cfg.dynamicSmemBytes = SM_BYTES;
    cfg.stream = 0;
    cudaLaunchAttribute attrs[1];
    attrs[0].id = cudaLaunchAttributeClusterDimension;
    attrs[0].val.clusterDim.x = CL;
    attrs[0].val.clusterDim.y = 1;
    attrs[0].val.clusterDim.z = 1;
    cfg.attrs = attrs;
    cfg.numAttrs = 1;

    cudaLaunchKernelEx(&cfg, lstm_cluster_kernel, x, Wih1, Whh1, bih1, bhh1,
                       Wih2, Whh2, bih2, bhh2, Wout, bout, out);
}

// round 5
// speedup vs baseline: 1.6235x; 1.1387x over previous
#include <cuda_runtime.h>
#include <cstdint>

// LSTMPredictor: B=256, T=1024, H=128, 2-layer LSTM + linear head.
// 32 clusters x 4 CTAs x 512 threads. Each CTA owns 32 hidden units per layer
// (128 gate rows). Whh1/Whh2 fp32 in SMEM (kp-major pair-interleaved for
// fma.rn.f32x2); Wih2 held in per-thread registers. Per thread: 2 rows x
// 8 batches x 16 k (k-split 8). h stored [batch][k], exchanged via DSMEM.
// Two-phase partial reduction (gbuf -> gsum) before the gate epilogue.

namespace {

constexpr int Bt = 256;
constexpr int Tt = 1024;
constexpr int Ht = 128;
constexpr int CL = 4;
constexpr int BC = 8;
constexpr int NTH = 512;

// smem offsets (floats)
constexpr int OFF_W1  = 0;            // Whh1: 64kp*64rq*4 = 16384
constexpr int OFF_W2H = 16384;        // Whh2: 16384
constexpr int OFF_H1  = 32768;        // 2 parity * 8 b * 128 k = 2048
constexpr int OFF_H2  = 34816;        // 2048
constexpr int OFF_G   = 36864;        // gbuf partials: (4j*8ks)*64rq*4 = 8192
constexpr int OFF_GS  = 45056;        // gsum: 4j*64rq*4 = 1024
constexpr int OFF_BS1 = 46080;        // 128
constexpr int OFF_WX  = 46208;        // 128
constexpr int OFF_BS2 = 46336;        // 128
constexpr int OFF_WO  = 46464;        // 128
constexpr int OFF_X   = 46592;        // 2*8
constexpr int OFF_BO  = 46608;        // 1 (+pad)
constexpr int SM_FLOATS = 46612;
constexpr int SM_BYTES = SM_FLOATS * 4;  // 186,448 B

typedef unsigned long long u64;

__device__ __forceinline__ u64 pk2(float a, float b) {
    u64 r;
    asm("mov.b64 %0, {%1,%2};" : "=l"(r) : "f"(a), "f"(b));
    return r;
}
__device__ __forceinline__ void fma2(u64& d, u64 a, u64 b) {
    asm("fma.rn.f32x2 %0, %1, %2, %3;" : "=l"(d) : "l"(a), "l"(b), "l"(d));
}
__device__ __forceinline__ float2 upk2(u64 v) {
    float2 f;
    asm("mov.b64 {%0,%1}, %2;" : "=f"(f.x), "=f"(f.y) : "l"(v));
    return f;
}
__device__ __forceinline__ uint32_t s2u(const void* p) {
    return (uint32_t)__cvta_generic_to_shared(p);
}
__device__ __forceinline__ void st_remote(uint32_t laddr, uint32_t peer, float v) {
    uint32_t r;
    asm("mapa.shared::cluster.u32 %0, %1, %2;" : "=r"(r) : "r"(laddr), "r"(peer));
    asm volatile("st.shared::cluster.f32 [%0], %1;" ::"r"(r), "f"(v) : "memory");
}
__device__ __forceinline__ void cl_arrive() {
    asm volatile("barrier.cluster.arrive.aligned;" ::: "memory");
}
__device__ __forceinline__ void cl_wait() {
    asm volatile("barrier.cluster.wait.aligned;" ::: "memory");
}
__device__ __forceinline__ float sigf(float x) {
    return 1.0f / (1.0f + __expf(-x));
}
__device__ __forceinline__ float tanh_fast(float x) {
    return 2.0f / (1.0f + __expf(-2.0f * x)) - 1.0f;
}

__global__ void __launch_bounds__(NTH, 1) lstm_cluster_kernel(
    const float* __restrict__ x, const float* __restrict__ Wih1,
    const float* __restrict__ Whh1, const float* __restrict__ bih1,
    const float* __restrict__ bhh1, const float* __restrict__ Wih2,
    const float* __restrict__ Whh2, const float* __restrict__ bih2,
    const float* __restrict__ bhh2, const float* __restrict__ Wout,
    const float* __restrict__ bout, float* __restrict__ out) {
    extern __shared__ float sm[];
    float* W1s = sm + OFF_W1;
    float* W2hs = sm + OFF_W2H;
    float* h1b = sm + OFF_H1;
    float* h2b = sm + OFF_H2;
    float* gb = sm + OFF_G;
    float* gs = sm + OFF_GS;
    float* bs1s = sm + OFF_BS1;
    float* wxs = sm + OFF_WX;
    float* bs2s = sm + OFF_BS2;
    float* wos = sm + OFF_WO;
    float* xS = sm + OFF_X;
    float* boS = sm + OFF_BO;

    const int tid = threadIdx.x;
    const int lane = tid & 31;
    const int warp = tid >> 5;
    const int rank = blockIdx.x & 3;
    const int bbase = (blockIdx.x >> 2) * BC;
    const int U0 = rank * 32;

    // ---- Whh1/Whh2 into SMEM pair-interleaved kp-major ----
    // float4 at [kp*256 + rq*4] = { w[2rq][2kp], w[2rq][2kp+1], w[2rq+1][2kp], w[2rq+1][2kp+1] }
    for (int idx = tid; idx < 64 * 64; idx += NTH) {
        const int kp = idx >> 6;
        const int rqi = idx & 63;
        const int k0 = kp * 2;
        const int lr0 = rqi * 2, lr1 = lr0 + 1;
        const int g0 = ((lr0 >> 5) << 7) + U0 + (lr0 & 31);
        const int g1 = ((lr1 >> 5) << 7) + U0 + (lr1 & 31);
        const int d = kp * 256 + rqi * 4;
        {
            float2 a = *reinterpret_cast<const float2*>(&Whh1[g0 * Ht + k0]);
            float2 b = *reinterpret_cast<const float2*>(&Whh1[g1 * Ht + k0]);
            *reinterpret_cast<float4*>(&W1s[d]) = make_float4(a.x, a.y, b.x, b.y);
        }
        {
            float2 a = *reinterpret_cast<const float2*>(&Whh2[g0 * Ht + k0]);
            float2 b = *reinterpret_cast<const float2*>(&Whh2[g1 * Ht + k0]);
            *reinterpret_cast<float4*>(&W2hs[d]) = make_float4(a.x, a.y, b.x, b.y);
        }
    }
    for (int lr = tid; lr < 128; lr += NTH) {
        const int grow = ((lr >> 5) << 7) + U0 + (lr & 31);
        bs1s[lr] = bih1[grow] + bhh1[grow];
        wxs[lr] = Wih1[grow];
        bs2s[lr] = bih2[grow] + bhh2[grow];
        wos[lr] = Wout[lr];
    }
    for (int i = tid; i < 2048; i += NTH) {
        h1b[i] = 0.0f;
        h2b[i] = 0.0f;
    }
    if (tid < BC) xS[tid] = x[(bbase + tid) * Tt + 0];
    if (tid == 0) boS[0] = bout[0];

    // ---- compute-phase mapping: ks = warp>>1 (k-split 8), rq = 0..63 ----
    const int ks = warp >> 1;
    const int koff = ks * 16;
    const int rq = ((warp & 1) << 5) | lane;
    const float* wA = W1s + ks * 2048 + rq * 4;   // 8 kp per warp
    const float* wBh = W2hs + ks * 2048 + rq * 4;

    // ---- Wih2 slice in registers: 2 rows x 16 k = 16 u64 ----
    u64 wi[16];
    {
        const int lr0 = rq * 2, lr1 = lr0 + 1;
        const int g0 = ((lr0 >> 5) << 7) + U0 + (lr0 & 31);
        const int g1 = ((lr1 >> 5) << 7) + U0 + (lr1 & 31);
#pragma unroll
        for (int it = 0; it < 4; ++it) {
            const int kb = koff + it * 4;
            const float4 a =
                *reinterpret_cast<const float4*>(&Wih2[g0 * Ht + kb]);
            const float4 b =
                *reinterpret_cast<const float4*>(&Wih2[g1 * Ht + kb]);
            wi[it * 4 + 0] = pk2(a.x, a.y);
            wi[it * 4 + 1] = pk2(a.z, a.w);
            wi[it * 4 + 2] = pk2(b.x, b.y);
            wi[it * 4 + 3] = pk2(b.z, b.w);
        }
    }
    __syncthreads();
    cl_arrive();
    cl_wait();  // peers zeroed before any remote stores

    const float bs1_0 = bs1s[2 * rq], bs1_1 = bs1s[2 * rq + 1];
    const float wx0 = wxs[2 * rq], wx1 = wxs[2 * rq + 1];
    const float bs2_0 = bs2s[2 * rq], bs2_1 = bs2s[2 * rq + 1];
    const float boutr = boS[0];

    // epilogue mapping (tid < 256): unit uu, batch bb
    const int uu = tid & 31;
    const int bb = (tid >> 5) & 7;
    const bool epi = tid < 256;
    const int hoff = bb * 128 + U0 + uu;
    const uint32_t h1u = s2u(h1b);
    const uint32_t h2u = s2u(h2b);
    const uint32_t p1 = (rank + 1) & 3, p2r = (rank + 2) & 3, p3 = (rank + 3) & 3;
    // gsum indices: j = (uu&1)*2 + (bb>>2); per gate g: rq' = g*16 + (uu>>1)
    int gidx[4];
    {
        const int j = (uu & 1) * 2 + (bb >> 2);
#pragma unroll
        for (int g = 0; g < 4; ++g)
            gidx[g] = (j * 64 + g * 16 + (uu >> 1)) * 4 + (bb & 3);
    }
    // phase1 mapping (tid < 256): slot (jp, rp)
    const int jp = tid >> 6;       // 0..3
    const int rp = tid & 63;       // 0..63

    float c1 = 0.0f, c2 = 0.0f;
    float xreg = (tid < BC && Tt > 1) ? x[(bbase + tid) * Tt + 1] : 0.0f;

    // GEMV (SMEM weights): acc[0..7]=row r0 b0..7 (k-paired), acc[8..15]=row r1
    auto gemv = [&](u64* acc, const float* wp, const float* hp) {
#pragma unroll
        for (int it = 0; it < 4; ++it) {
            const ulonglong2 wqa =
                *reinterpret_cast<const ulonglong2*>(wp + it * 512);
            const ulonglong2 wqb =
                *reinterpret_cast<const ulonglong2*>(wp + it * 512 + 256);
#pragma unroll
            for (int b = 0; b < 8; ++b) {
                const ulonglong2 hv = *reinterpret_cast<const ulonglong2*>(
                    hp + b * 128 + koff + it * 4);
                fma2(acc[b], wqa.x, hv.x);
                fma2(acc[8 + b], wqa.y, hv.x);
                fma2(acc[b], wqb.x, hv.y);
                fma2(acc[8 + b], wqb.y, hv.y);
            }
        }
    };
    // GEMV with register weights (Wih2)
    auto gemv_reg = [&](u64* acc, const float* hp) {
#pragma unroll
        for (int it = 0; it < 4; ++it) {
#pragma unroll
            for (int b = 0; b < 8; ++b) {
                const ulonglong2 hv = *reinterpret_cast<const ulonglong2*>(
                    hp + b * 128 + koff + it * 4);
                fma2(acc[b], wi[it * 4 + 0], hv.x);
                fma2(acc[8 + b], wi[it * 4 + 2], hv.x);
                fma2(acc[b], wi[it * 4 + 1], hv.y);
                fma2(acc[8 + b], wi[it * 4 + 3], hv.y);
            }
        }
    };
    auto redstore = [&](u64* acc) {
#pragma unroll
        for (int s = 0; s < 2; ++s)
#pragma unroll
            for (int bq = 0; bq < 2; ++bq) {
                float2 t0 = upk2(acc[s * 8 + bq * 4 + 0]);
                float2 t1 = upk2(acc[s * 8 + bq * 4 + 1]);
                float2 t2 = upk2(acc[s * 8 + bq * 4 + 2]);
                float2 t3 = upk2(acc[s * 8 + bq * 4 + 3]);
                const int j = s * 2 + bq;
                reinterpret_cast<float4*>(gb)[(j * 8 + ks) * 64 + rq] =
                    make_float4(t0.x + t0.y, t1.x + t1.y, t2.x + t2.y,
                                t3.x + t3.y);
            }
    };
    // phase1: sum 8 k-split partials into gsum (tid<256)
    auto reduce_partials = [&]() {
        if (epi) {
            const float4* src = reinterpret_cast<const float4*>(gb) +
                                (jp * 8) * 64 + rp;
            float4 a = src[0];
#pragma unroll
            for (int k = 1; k < 8; ++k) {
                const float4 v = src[k * 64];
                a.x += v.x; a.y += v.y; a.z += v.z; a.w += v.w;
            }
            reinterpret_cast<float4*>(gs)[jp * 64 + rp] = a;
        }
    };

    for (int t = 0; t < Tt; ++t) {
        const int p = t & 1;
        const float* h1prev = h1b + (p ^ 1) * 1024;
        const float* h2prev = h2b + (p ^ 1) * 1024;
        float* h1cur = h1b + p * 1024;
        float* h2cur = h2b + p * 1024;

        // ===== stage A: gates1 = Whh1 @ h1(t-1) + x*wih1 + b (partials) =====
        {
            u64 A[16];
            if (ks == 0) {
                const float* xp = xS + p * 8;
#pragma unroll
                for (int b = 0; b < 8; ++b) {
                    const float xb = xp[b];
                    A[b] = pk2(bs1_0 + xb * wx0, 0.0f);
                    A[8 + b] = pk2(bs1_1 + xb * wx1, 0.0f);
                }
            } else {
#pragma unroll
                for (int i = 0; i < 16; ++i) A[i] = 0ull;
            }
            gemv(A, wA, h1prev);
            redstore(A);
        }

        // barrier2(t-1) hidden behind stage A; then output(t-1)
        if (t > 0) {
            cl_wait();
            if (tid < 64) {
                const int ow = tid >> 5;
                const int bl = rank * 2 + ow;
                const float4 hv = *reinterpret_cast<const float4*>(
                    h2prev + bl * 128 + lane * 4);
                const float4 wv =
                    *reinterpret_cast<const float4*>(wos + lane * 4);
                float s = hv.x * wv.x + hv.y * wv.y + hv.z * wv.z + hv.w * wv.w;
                s += __shfl_xor_sync(0xffffffffu, s, 16);
                s += __shfl_xor_sync(0xffffffffu, s, 8);
                s += __shfl_xor_sync(0xffffffffu, s, 4);
                s += __shfl_xor_sync(0xffffffffu, s, 2);
                s += __shfl_xor_sync(0xffffffffu, s, 1);
                if (lane == 0) out[(bbase + bl) * Tt + (t - 1)] = s + boutr;
            }
        }
        __syncthreads();
        reduce_partials();
        __syncthreads();

        // ===== epilogue A: c1/h1 update + cluster push =====
        if (epi) {
            const float gi = gs[gidx[0]];
            const float gf = gs[gidx[1]];
            const float gg = gs[gidx[2]];
            const float go = gs[gidx[3]];
            c1 = sigf(gf) * c1 + sigf(gi) * tanh_fast(gg);
            const float h1v = sigf(go) * tanh_fast(c1);
            h1cur[hoff] = h1v;
            const uint32_t la = h1u + (uint32_t)(p * 1024 + hoff) * 4u;
            st_remote(la, p1, h1v);
            st_remote(la, p2r, h1v);
            st_remote(la, p3, h1v);
        }
        if (tid < BC) {
            xS[(p ^ 1) * 8 + tid] = xreg;
            if (t + 2 < Tt) xreg = x[(bbase + tid) * Tt + (t + 2)];
        }
        cl_arrive();  // barrier1: h1(t) in flight

        // ===== stage B part 1 (overlaps barrier1): Whh2 @ h2(t-1) + b =====
        u64 Bk[16];
        if (ks == 0) {
#pragma unroll
            for (int b = 0; b < 8; ++b) {
                Bk[b] = pk2(bs2_0, 0.0f);
                Bk[8 + b] = pk2(bs2_1, 0.0f);
            }
        } else {
#pragma unroll
            for (int i = 0; i < 16; ++i) Bk[i] = 0ull;
        }
        gemv(Bk, wBh, h2prev);
        cl_wait();  // barrier1: full h1(t) visible

        // ===== stage B part 2: += Wih2(regs) @ h1(t) =====
        gemv_reg(Bk, h1cur);
        redstore(Bk);
        __syncthreads();
        reduce_partials();
        __syncthreads();

        // ===== epilogue B: c2/h2 update + cluster push =====
        if (epi) {
            const float gi = gs[gidx[0]];
            const float gf = gs[gidx[1]];
            const float gg = gs[gidx[2]];
            const float go = gs[gidx[3]];
            c2 = sigf(gf) * c2 + sigf(gi) * tanh_fast(gg);
            const float h2v = sigf(go) * tanh_fast(c2);
            h2cur[hoff] = h2v;
            const uint32_t la = h2u + (uint32_t)(p * 1024 + hoff) * 4u;
            st_remote(la, p1, h2v);
            st_remote(la, p2r, h2v);
            st_remote(la, p3, h2v);
        }
        cl_arrive();  // barrier2: h2(t) in flight (hidden behind next stage A)
    }

    // drain: last output
    cl_wait();
    if (tid < 64) {
        const int ow = tid >> 5;
        const int bl = rank * 2 + ow;
        const float* h2last = h2b + ((Tt - 1) & 1) * 1024;
        const float4 hv =
            *reinterpret_cast<const float4*>(h2last + bl * 128 + lane * 4);
        const float4 wv = *reinterpret_cast<const float4*>(wos + lane * 4);
        float s = hv.x * wv.x + hv.y * wv.y + hv.z * wv.z + hv.w * wv.w;
        s += __shfl_xor_sync(0xffffffffu, s, 16);
        s += __shfl_xor_sync(0xffffffffu, s, 8);
        s += __shfl_xor_sync(0xffffffffu, s, 4);
        s += __shfl_xor_sync(0xffffffffu, s, 2);
        s += __shfl_xor_sync(0xffffffffu, s, 1);
        if (lane == 0) out[(bbase + bl) * Tt + (Tt - 1)] = s + boutr;
    }
}

}  // namespace

extern "C" void kernel_launch(void* const* d_in, const int* in_sizes, int n_in,
                              void* d_out, int out_size) {
    (void)in_sizes;
    (void)n_in;
    (void)out_size;
    const float* x = (const float*)d_in[0];
    const float* Wih1 = (const float*)d_in[1];
    const float* Whh1 = (const float*)d_in[2];
    const float* bih1 = (const float*)d_in[3];
    const float* bhh1 = (const float*)d_in[4];
    const float* Wih2 = (const float*)d_in[5];
    const float* Whh2 = (const float*)d_in[6];
    const float* bih2 = (const float*)d_in[7];
    const float* bhh2 = (const float*)d_in[8];
    const float* Wout = (const float*)d_in[9];
    const float* bout = (const float*)d_in[10];
    float* out = (float*)d_out;

    cudaFuncSetAttribute(lstm_cluster_kernel,
                         cudaFuncAttributeMaxDynamicSharedMemorySize, SM_BYTES);

    cudaLaunchConfig_t cfg = {};
    cfg.gridDim = dim3((Bt / BC) * CL, 1, 1);  // 128 CTAs = 32 clusters of 4
    cfg.blockDim = dim3(NTH, 1, 1);
    cfg.dynamicSmemBytes = SM_BYTES;
    cfg.stream = 0;
    cudaLaunchAttribute attrs[1];
    attrs[0].id = cudaLaunchAttributeClusterDimension;
    attrs[0].val.clusterDim.x = CL;
    attrs[0].val.clusterDim.y = 1;
    attrs[0].val.clusterDim.z = 1;
    cfg.attrs = attrs;
    cfg.numAttrs = 1;

    cudaLaunchKernelEx(&cfg, lstm_cluster_kernel, x, Wih1, Whh1, bih1, bhh1,
                       Wih2, Whh2, bih2, bhh2, Wout, bout, out);
}

// round 6
// speedup vs baseline: 1.6838x; 1.0371x over previous
#include <cuda_runtime.h>
#include <cstdint>

// LSTMPredictor: B=256, T=1024, H=128, 2-layer LSTM + linear head.
// 32 clusters x 4 CTAs x 512 threads, warp-specialized software pipeline:
//   Q = warps 8..15: A-gemv (Whh1@h1), Bh-gemv (Whh2@h2), output head.
//   P = warps 0..7 : reductions, gate epilogues (c/h updates, DSMEM pushes),
//                    Bi-gemv (Wih2@h1).
// Named barriers: bar1 = A partials ready (Q->P), bar2 = Bh partials ready
// (Q->P), bar3 = P-internal reduce->epi. Two cluster barriers per step
// (h1 ready, h2 ready), both overlapped with the other group's gemv.
// Weights fp32: Whh1 in SMEM; Whh2/Wih2 half SMEM + half registers.
// All gemvs: ksplit 4 (KW=32) x rowsplit 2, packed fma.rn.f32x2.

namespace {

constexpr int Bt = 256;
constexpr int Tt = 1024;
constexpr int Ht = 128;
constexpr int CL = 4;
constexpr int BC = 8;
constexpr int NTH = 512;

// smem offsets (floats)
constexpr int OFF_W1  = 0;         // Whh1 full: 64kp*64rq*4 = 16384
constexpr int OFF_W2H = 16384;     // Whh2 low-half (k 0..15 of each slice): 8192
constexpr int OFF_W2I = 24576;     // Wih2 low-half: 8192
constexpr int OFF_H1  = 32768;     // 2 parity * 8 b * 128 k = 2048
constexpr int OFF_H2  = 34816;     // 2048
constexpr int OFF_GA  = 36864;     // A partials: 4j*4ks*64rq*4 = 4096
constexpr int OFF_GB  = 40960;     // B partials: 4j*8s*64rq*4 = 8192
constexpr int OFF_GS  = 49152;     // reduced gates: 4j*64rq*4 = 1024
constexpr int OFF_BS1 = 50176;     // 128
constexpr int OFF_WX  = 50304;     // 128
constexpr int OFF_BS2 = 50432;     // 128
constexpr int OFF_WO  = 50560;     // 128
constexpr int OFF_BO  = 50688;     // 4
constexpr int SM_FLOATS = 50692;
constexpr int SM_BYTES = SM_FLOATS * 4;  // 202,768 B

typedef unsigned long long u64;

__device__ __forceinline__ u64 pk2(float a, float b) {
    u64 r;
    asm("mov.b64 %0, {%1,%2};" : "=l"(r) : "f"(a), "f"(b));
    return r;
}
__device__ __forceinline__ void fma2(u64& d, u64 a, u64 b) {
    asm("fma.rn.f32x2 %0, %1, %2, %3;" : "=l"(d) : "l"(a), "l"(b), "l"(d));
}
__device__ __forceinline__ float2 upk2(u64 v) {
    float2 f;
    asm("mov.b64 {%0,%1}, %2;" : "=f"(f.x), "=f"(f.y) : "l"(v));
    return f;
}
__device__ __forceinline__ uint32_t s2u(const void* p) {
    return (uint32_t)__cvta_generic_to_shared(p);
}
__device__ __forceinline__ void st_remote(uint32_t laddr, uint32_t peer, float v) {
    uint32_t r;
    asm("mapa.shared::cluster.u32 %0, %1, %2;" : "=r"(r) : "r"(laddr), "r"(peer));
    asm volatile("st.shared::cluster.f32 [%0], %1;" ::"r"(r), "f"(v) : "memory");
}
__device__ __forceinline__ void cl_arrive() {
    asm volatile("barrier.cluster.arrive;" ::: "memory");
}
__device__ __forceinline__ void cl_wait() {
    asm volatile("barrier.cluster.wait;" ::: "memory");
}
__device__ __forceinline__ void bar_sync(int id, int cnt) {
    asm volatile("bar.sync %0, %1;" ::"r"(id), "r"(cnt) : "memory");
}
__device__ __forceinline__ void bar_arrive(int id, int cnt) {
    asm volatile("bar.arrive %0, %1;" ::"r"(id), "r"(cnt) : "memory");
}
__device__ __forceinline__ float sigf(float x) {
    return 1.0f / (1.0f + __expf(-x));
}
__device__ __forceinline__ float tanh_fast(float x) {
    return 2.0f / (1.0f + __expf(-2.0f * x)) - 1.0f;
}

__global__ void __launch_bounds__(NTH, 1) lstm_cluster_kernel(
    const float* __restrict__ x, const float* __restrict__ Wih1,
    const float* __restrict__ Whh1, const float* __restrict__ bih1,
    const float* __restrict__ bhh1, const float* __restrict__ Wih2,
    const float* __restrict__ Whh2, const float* __restrict__ bih2,
    const float* __restrict__ bhh2, const float* __restrict__ Wout,
    const float* __restrict__ bout, float* __restrict__ out) {
    extern __shared__ float sm[];
    float* W1s = sm + OFF_W1;
    float* W2hs = sm + OFF_W2H;
    float* W2is = sm + OFF_W2I;
    float* h1b = sm + OFF_H1;
    float* h2b = sm + OFF_H2;
    float* gbA = sm + OFF_GA;
    float* gbB = sm + OFF_GB;
    float* gs = sm + OFF_GS;
    float* bs1s = sm + OFF_BS1;
    float* wxs = sm + OFF_WX;
    float* bs2s = sm + OFF_BS2;
    float* wos = sm + OFF_WO;
    float* boS = sm + OFF_BO;

    const int tid = threadIdx.x;
    const int lane = tid & 31;
    const int warp = tid >> 5;
    const int rank = blockIdx.x & 3;
    const int bbase = (blockIdx.x >> 2) * BC;
    const int U0 = rank * 32;

    // ---- Whh1 full, pair-interleaved kp-major ----
    for (int idx = tid; idx < 64 * 64; idx += NTH) {
        const int kp = idx >> 6;
        const int rqi = idx & 63;
        const int k0 = kp * 2;
        const int lr0 = rqi * 2, lr1 = lr0 + 1;
        const int g0 = ((lr0 >> 5) << 7) + U0 + (lr0 & 31);
        const int g1 = ((lr1 >> 5) << 7) + U0 + (lr1 & 31);
        float2 a = *reinterpret_cast<const float2*>(&Whh1[g0 * Ht + k0]);
        float2 b = *reinterpret_cast<const float2*>(&Whh1[g1 * Ht + k0]);
        *reinterpret_cast<float4*>(&W1s[kp * 256 + rqi * 4]) =
            make_float4(a.x, a.y, b.x, b.y);
    }
    // ---- Whh2 / Wih2 low halves (per k-slice: first 16 k) ----
    for (int idx = tid; idx < 2048; idx += NTH) {
        const int ks = idx >> 9;
        const int kpl = (idx >> 6) & 7;
        const int rqi = idx & 63;
        const int k0 = ks * 32 + kpl * 2;
        const int lr0 = rqi * 2, lr1 = lr0 + 1;
        const int g0 = ((lr0 >> 5) << 7) + U0 + (lr0 & 31);
        const int g1 = ((lr1 >> 5) << 7) + U0 + (lr1 & 31);
        const int d = ks * 2048 + kpl * 256 + rqi * 4;
        {
            float2 a = *reinterpret_cast<const float2*>(&Whh2[g0 * Ht + k0]);
            float2 b = *reinterpret_cast<const float2*>(&Whh2[g1 * Ht + k0]);
            *reinterpret_cast<float4*>(&W2hs[d]) = make_float4(a.x, a.y, b.x, b.y);
        }
        {
            float2 a = *reinterpret_cast<const float2*>(&Wih2[g0 * Ht + k0]);
            float2 b = *reinterpret_cast<const float2*>(&Wih2[g1 * Ht + k0]);
            *reinterpret_cast<float4*>(&W2is[d]) = make_float4(a.x, a.y, b.x, b.y);
        }
    }
    for (int lr = tid; lr < 128; lr += NTH) {
        const int grow = ((lr >> 5) << 7) + U0 + (lr & 31);
        bs1s[lr] = bih1[grow] + bhh1[grow];
        wxs[lr] = Wih1[grow];
        bs2s[lr] = bih2[grow] + bhh2[grow];
        wos[lr] = Wout[lr];
    }
    for (int i = tid; i < 2048; i += NTH) {
        h1b[i] = 0.0f;
        h2b[i] = 0.0f;
    }
    if (tid == 0) boS[0] = bout[0];
    __syncthreads();
    cl_arrive();
    cl_wait();  // gen0: peers' buffers zeroed

    const uint32_t h1u = s2u(h1b);
    const uint32_t h2u = s2u(h2b);
    const uint32_t p1 = (rank + 1) & 3, p2r = (rank + 2) & 3, p3 = (rank + 3) & 3;

    // shared gemv helpers (tiling: 64 rows/warp, 8 batches, KW=32)
    auto gemv_full = [&](u64* acc, const float* wp, const float* hp, int koff) {
#pragma unroll
        for (int it = 0; it < 8; ++it) {
            const ulonglong2 wqa = *reinterpret_cast<const ulonglong2*>(wp + it * 512);
            const ulonglong2 wqb = *reinterpret_cast<const ulonglong2*>(wp + it * 512 + 256);
#pragma unroll
            for (int b = 0; b < 8; ++b) {
                const ulonglong2 hv = *reinterpret_cast<const ulonglong2*>(
                    hp + b * 128 + koff + it * 4);
                fma2(acc[b], wqa.x, hv.x);
                fma2(acc[8 + b], wqa.y, hv.x);
                fma2(acc[b], wqb.x, hv.y);
                fma2(acc[8 + b], wqb.y, hv.y);
            }
        }
    };
    auto gemv_half = [&](u64* acc, const float* wp, const u64* wr,
                         const float* hp, int koff) {
#pragma unroll
        for (int it = 0; it < 4; ++it) {  // SMEM half: k in [koff, koff+16)
            const ulonglong2 wqa = *reinterpret_cast<const ulonglong2*>(wp + it * 512);
            const ulonglong2 wqb = *reinterpret_cast<const ulonglong2*>(wp + it * 512 + 256);
#pragma unroll
            for (int b = 0; b < 8; ++b) {
                const ulonglong2 hv = *reinterpret_cast<const ulonglong2*>(
                    hp + b * 128 + koff + it * 4);
                fma2(acc[b], wqa.x, hv.x);
                fma2(acc[8 + b], wqa.y, hv.x);
                fma2(acc[b], wqb.x, hv.y);
                fma2(acc[8 + b], wqb.y, hv.y);
            }
        }
#pragma unroll
        for (int it = 0; it < 4; ++it) {  // reg half: k in [koff+16, koff+32)
#pragma unroll
            for (int b = 0; b < 8; ++b) {
                const ulonglong2 hv = *reinterpret_cast<const ulonglong2*>(
                    hp + b * 128 + koff + 16 + it * 4);
                fma2(acc[b], wr[it * 4 + 0], hv.x);
                fma2(acc[8 + b], wr[it * 4 + 2], hv.x);
                fma2(acc[b], wr[it * 4 + 1], hv.y);
                fma2(acc[8 + b], wr[it * 4 + 3], hv.y);
            }
        }
    };

    if (tid >= 256) {
        // ================= group Q: A-gemv, Bh-gemv, output =================
        const int qw = warp - 8;
        const int ks = qw >> 1;
        const int koff = ks * 32;
        const int rq = ((qw & 1) << 5) | lane;
        const float* wA = W1s + ks * 16 * 256 + rq * 4;
        const float* wBh = W2hs + ks * 2048 + rq * 4;
        const float bs1_0 = bs1s[2 * rq], bs1_1 = bs1s[2 * rq + 1];
        const float wx0 = wxs[2 * rq], wx1 = wxs[2 * rq + 1];

        // Whh2 high half in regs (k in [koff+16, koff+32), 2 rows)
        u64 whr[16];
        {
            const int lr0 = rq * 2, lr1 = lr0 + 1;
            const int g0 = ((lr0 >> 5) << 7) + U0 + (lr0 & 31);
            const int g1 = ((lr1 >> 5) << 7) + U0 + (lr1 & 31);
#pragma unroll
            for (int it = 0; it < 4; ++it) {
                const int kb = koff + 16 + it * 4;
                const float4 a = *reinterpret_cast<const float4*>(&Whh2[g0 * Ht + kb]);
                const float4 b = *reinterpret_cast<const float4*>(&Whh2[g1 * Ht + kb]);
                whr[it * 4 + 0] = pk2(a.x, a.y);
                whr[it * 4 + 1] = pk2(a.z, a.w);
                whr[it * 4 + 2] = pk2(b.x, b.y);
                whr[it * 4 + 3] = pk2(b.z, b.w);
            }
        }

        auto redstoreA = [&](u64* acc) {
#pragma unroll
            for (int s = 0; s < 2; ++s)
#pragma unroll
                for (int bq = 0; bq < 2; ++bq) {
                    float2 t0 = upk2(acc[s * 8 + bq * 4 + 0]);
                    float2 t1 = upk2(acc[s * 8 + bq * 4 + 1]);
                    float2 t2 = upk2(acc[s * 8 + bq * 4 + 2]);
                    float2 t3 = upk2(acc[s * 8 + bq * 4 + 3]);
                    const int j = s * 2 + bq;
                    reinterpret_cast<float4*>(gbA)[(j * 4 + ks) * 64 + rq] =
                        make_float4(t0.x + t0.y, t1.x + t1.y, t2.x + t2.y, t3.x + t3.y);
                }
        };
        auto redstoreBh = [&](u64* acc) {
#pragma unroll
            for (int s = 0; s < 2; ++s)
#pragma unroll
                for (int bq = 0; bq < 2; ++bq) {
                    float2 t0 = upk2(acc[s * 8 + bq * 4 + 0]);
                    float2 t1 = upk2(acc[s * 8 + bq * 4 + 1]);
                    float2 t2 = upk2(acc[s * 8 + bq * 4 + 2]);
                    float2 t3 = upk2(acc[s * 8 + bq * 4 + 3]);
                    const int j = s * 2 + bq;
                    reinterpret_cast<float4*>(gbB)[(j * 8 + 4 + ks) * 64 + rq] =
                        make_float4(t0.x + t0.y, t1.x + t1.y, t2.x + t2.y, t3.x + t3.y);
                }
        };

        // x pipeline (warps with ks==0, lane<8): xu = x(t+1) at A(t+1) time
        float xu = 0.0f, xn = 0.0f;
        if (ks == 0 && lane < 8) {
            xu = x[(bbase + lane) * Tt + 0];
            if (Tt > 1) xn = x[(bbase + lane) * Tt + 1];
        }

        // prologue: A(0) with h1(-1)=0, x(0)
        {
            u64 A[16];
            if (ks == 0) {
#pragma unroll
                for (int b = 0; b < 8; ++b) {
                    const float xb = __shfl_sync(0xffffffffu, xu, b);
                    A[b] = pk2(bs1_0 + xb * wx0, 0.0f);
                    A[8 + b] = pk2(bs1_1 + xb * wx1, 0.0f);
                }
            } else {
#pragma unroll
                for (int i = 0; i < 16; ++i) A[i] = 0ull;
            }
            gemv_full(A, wA, h1b + 1024, koff);  // h1 parity 1 (zeros)
            redstoreA(A);
            bar_arrive(1, 512);
        }

        for (int t = 0; t < Tt; ++t) {
            const int p = t & 1;
            // ---- Bh(t): Whh2 @ h2(t-1), zero-init (bias lives in Bi) ----
            {
                u64 Bk[16];
#pragma unroll
                for (int i = 0; i < 16; ++i) Bk[i] = 0ull;
                gemv_half(Bk, wBh, whr, h2b + (p ^ 1) * 1024, koff);
                redstoreBh(Bk);
                bar_arrive(2, 512);
            }
            cl_arrive();  // h1(t) phase
            cl_wait();    // h1(t) visible everywhere

            // ---- A(t+1): Whh1 @ h1(t) + x(t+1)*wih1 + b ----
            if (t + 1 < Tt) {
                u64 A[16];
                if (ks == 0) {
                    const float xc = xn;
                    if (lane < 8 && t + 2 < Tt)
                        xn = x[(bbase + lane) * Tt + (t + 2)];
#pragma unroll
                    for (int b = 0; b < 8; ++b) {
                        const float xb = __shfl_sync(0xffffffffu, xc, b);
                        A[b] = pk2(bs1_0 + xb * wx0, 0.0f);
                        A[8 + b] = pk2(bs1_1 + xb * wx1, 0.0f);
                    }
                } else {
#pragma unroll
                    for (int i = 0; i < 16; ++i) A[i] = 0ull;
                }
                gemv_full(A, wA, h1b + p * 1024, koff);
                redstoreA(A);
                bar_arrive(1, 512);
            }
            cl_arrive();  // h2(t) phase
            cl_wait();    // h2(t) visible everywhere

            // ---- output(t) on warps 14,15 ----
            if (warp >= 14) {
                const int ow = warp - 14;
                const int bl = rank * 2 + ow;
                const float4 hv = *reinterpret_cast<const float4*>(
                    h2b + p * 1024 + bl * 128 + lane * 4);
                const float4 wv = *reinterpret_cast<const float4*>(wos + lane * 4);
                float s = hv.x * wv.x + hv.y * wv.y + hv.z * wv.z + hv.w * wv.w;
                s += __shfl_xor_sync(0xffffffffu, s, 16);
                s += __shfl_xor_sync(0xffffffffu, s, 8);
                s += __shfl_xor_sync(0xffffffffu, s, 4);
                s += __shfl_xor_sync(0xffffffffu, s, 2);
                s += __shfl_xor_sync(0xffffffffu, s, 1);
                if (lane == 0) out[(bbase + bl) * Tt + t] = s + boS[0];
            }
        }
    } else {
        // ====== group P: reductions, epilogues, h pushes, Bi-gemv ======
        const int pw = warp;
        const int ks = pw >> 1;
        const int koff = ks * 32;
        const int rq = ((pw & 1) << 5) | lane;
        const float* wBi = W2is + ks * 2048 + rq * 4;
        const float bs2_0 = bs2s[2 * rq], bs2_1 = bs2s[2 * rq + 1];

        // Wih2 high half in regs
        u64 wir[16];
        {
            const int lr0 = rq * 2, lr1 = lr0 + 1;
            const int g0 = ((lr0 >> 5) << 7) + U0 + (lr0 & 31);
            const int g1 = ((lr1 >> 5) << 7) + U0 + (lr1 & 31);
#pragma unroll
            for (int it = 0; it < 4; ++it) {
                const int kb = koff + 16 + it * 4;
                const float4 a = *reinterpret_cast<const float4*>(&Wih2[g0 * Ht + kb]);
                const float4 b = *reinterpret_cast<const float4*>(&Wih2[g1 * Ht + kb]);
                wir[it * 4 + 0] = pk2(a.x, a.y);
                wir[it * 4 + 1] = pk2(a.z, a.w);
                wir[it * 4 + 2] = pk2(b.x, b.y);
                wir[it * 4 + 3] = pk2(b.z, b.w);
            }
        }

        // epilogue mapping: unit uu, batch bb
        const int uu = tid & 31;
        const int bb = tid >> 5;
        const int hoff = bb * 128 + U0 + uu;
        int gidx[4];
        {
            const int j = (uu & 1) * 2 + (bb >> 2);
#pragma unroll
            for (int g = 0; g < 4; ++g)
                gidx[g] = (j * 64 + g * 16 + (uu >> 1)) * 4 + (bb & 3);
        }
        // reduce mapping
        const int jp = tid >> 6;  // 0..3
        const int rp = tid & 63;  // 0..63

        float c1 = 0.0f, c2 = 0.0f;

        auto redstoreBi = [&](u64* acc) {
#pragma unroll
            for (int s = 0; s < 2; ++s)
#pragma unroll
                for (int bq = 0; bq < 2; ++bq) {
                    float2 t0 = upk2(acc[s * 8 + bq * 4 + 0]);
                    float2 t1 = upk2(acc[s * 8 + bq * 4 + 1]);
                    float2 t2 = upk2(acc[s * 8 + bq * 4 + 2]);
                    float2 t3 = upk2(acc[s * 8 + bq * 4 + 3]);
                    const int j = s * 2 + bq;
                    reinterpret_cast<float4*>(gbB)[(j * 8 + ks) * 64 + rq] =
                        make_float4(t0.x + t0.y, t1.x + t1.y, t2.x + t2.y, t3.x + t3.y);
                }
        };

        for (int t = 0; t < Tt; ++t) {
            const int p = t & 1;
            float* h1cur = h1b + p * 1024;
            float* h2cur = h2b + p * 1024;

            // ---- reduceA(t): sum 4 k-split partials ----
            bar_sync(1, 512);  // A(t) partials ready (Q)
            {
                const float4* src = reinterpret_cast<const float4*>(gbA) + (jp * 4) * 64 + rp;
                float4 a = src[0];
#pragma unroll
                for (int k = 1; k < 4; ++k) {
                    const float4 v = src[k * 64];
                    a.x += v.x; a.y += v.y; a.z += v.z; a.w += v.w;
                }
                reinterpret_cast<float4*>(gs)[jp * 64 + rp] = a;
            }
            bar_sync(3, 256);
            // ---- epiA(t): c1/h1 update + cluster push ----
            {
                const float gi = gs[gidx[0]];
                const float gf = gs[gidx[1]];
                const float gg = gs[gidx[2]];
                const float go = gs[gidx[3]];
                c1 = sigf(gf) * c1 + sigf(gi) * tanh_fast(gg);
                const float h1v = sigf(go) * tanh_fast(c1);
                h1cur[hoff] = h1v;
                const uint32_t la = h1u + (uint32_t)(p * 1024 + hoff) * 4u;
                st_remote(la, p1, h1v);
                st_remote(la, p2r, h1v);
                st_remote(la, p3, h1v);
            }
            cl_arrive();  // h1(t) phase
            cl_wait();    // full h1(t) visible

            // ---- Bi(t): Wih2 @ h1(t) + bias(b2) ----
            {
                u64 Bk[16];
                if (ks == 0) {
#pragma unroll
                    for (int b = 0; b < 8; ++b) {
                        Bk[b] = pk2(bs2_0, 0.0f);
                        Bk[8 + b] = pk2(bs2_1, 0.0f);
                    }
                } else {
#pragma unroll
                    for (int i = 0; i < 16; ++i) Bk[i] = 0ull;
                }
                gemv_half(Bk, wBi, wir, h1cur, koff);
                redstoreBi(Bk);
            }
            bar_sync(2, 512);  // Bh(t) partials ready (Q) + own stores ordered
            // ---- reduceB(t): sum 8 partials ----
            {
                const float4* src = reinterpret_cast<const float4*>(gbB) + (jp * 8) * 64 + rp;
                float4 a = src[0];
#pragma unroll
                for (int k = 1; k < 8; ++k) {
                    const float4 v = src[k * 64];
                    a.x += v.x; a.y += v.y; a.z += v.z; a.w += v.w;
                }
                reinterpret_cast<float4*>(gs)[jp * 64 + rp] = a;
            }
            bar_sync(3, 256);
            // ---- epiB(t): c2/h2 update + cluster push ----
            {
                const float gi = gs[gidx[0]];
                const float gf = gs[gidx[1]];
                const float gg = gs[gidx[2]];
                const float go = gs[gidx[3]];
                c2 = sigf(gf) * c2 + sigf(gi) * tanh_fast(gg);
                const float h2v = sigf(go) * tanh_fast(c2);
                h2cur[hoff] = h2v;
                const uint32_t la = h2u + (uint32_t)(p * 1024 + hoff) * 4u;
                st_remote(la, p1, h2v);
                st_remote(la, p2r, h2v);
                st_remote(la, p3, h2v);
            }
            cl_arrive();  // h2(t) phase
            cl_wait();
        }
    }
}

}  // namespace

extern "C" void kernel_launch(void* const* d_in, const int* in_sizes, int n_in,
                              void* d_out, int out_size) {
    (void)in_sizes;
    (void)n_in;
    (void)out_size;
    const float* x = (const float*)d_in[0];
    const float* Wih1 = (const float*)d_in[1];
    const float* Whh1 = (const float*)d_in[2];
    const float* bih1 = (const float*)d_in[3];
    const float* bhh1 = (const float*)d_in[4];
    const float* Wih2 = (const float*)d_in[5];
    const float* Whh2 = (const float*)d_in[6];
    const float* bih2 = (const float*)d_in[7];
    const float* bhh2 = (const float*)d_in[8];
    const float* Wout = (const float*)d_in[9];
    const float* bout = (const float*)d_in[10];
    float* out = (float*)d_out;

    cudaFuncSetAttribute(lstm_cluster_kernel,
                         cudaFuncAttributeMaxDynamicSharedMemorySize, SM_BYTES);

    cudaLaunchConfig_t cfg = {};
    cfg.gridDim = dim3((Bt / BC) * CL, 1, 1);  // 128 CTAs = 32 clusters of 4
    cfg.blockDim = dim3(NTH, 1, 1);
    cfg.dynamicSmemBytes = SM_BYTES;
    cfg.stream = 0;
    cudaLaunchAttribute attrs[1];
    attrs[0].id = cudaLaunchAttributeClusterDimension;
    attrs[0].val.clusterDim.x = CL;
    attrs[0].val.clusterDim.y = 1;
    attrs[0].val.clusterDim.z = 1;
    cfg.attrs = attrs;
    cfg.numAttrs = 1;

    cudaLaunchKernelEx(&cfg, lstm_cluster_kernel, x, Wih1, Whh1, bih1, bhh1,
                       Wih2, Whh2, bih2, bhh2, Wout, bout, out);
}

// round 8
// speedup vs baseline: 2.8419x; 1.6877x over previous
#include <cuda_runtime.h>
#include <cstdint>

// LSTMPredictor: B=256, T=1024, H=128, 2-layer LSTM + linear head.
// 32 clusters x 4 CTAs x 256 threads. Each CTA owns 32 hidden units/layer
// (128 gate rows, r = gate*32 + unit). The three per-step matvecs run on
// per-warp tensor cores via mma.sync m16n8k8 tf32 (arch-generic PTX ->
// HMMA fallback pipe on sm_103):
//   D1 = Whh1 @ h1(t-1)                 (+ x*wih1 + bias in epilogue)
//   D2 = Whh2 @ h2(t-1) + Wih2 @ h1(t)  (+ bias in epilogue)
// All three weight matrices live in REGISTERS as pre-built A-fragments
// (64 tf32 regs per matrix per thread; 16 rows/warp, full K=128).
// h vectors stored TRANSPOSED [k][batch] in SMEM (conflict-free B-fragment
// loads), double-buffered by parity, exchanged via DSMEM stores + 2 cluster
// barriers per step. Gates staged via SMEM [row][batch] for the epilogue.

namespace {

constexpr int Bt = 256;
constexpr int Tt = 1024;
constexpr int Ht = 128;
constexpr int CL = 4;
constexpr int BC = 8;
constexpr int NTH = 256;

// smem (floats)
constexpr int OFF_HT1 = 0;      // h1 transposed: 2 parity x 128k x 8b
constexpr int OFF_HT2 = 2048;   // h2 transposed
constexpr int OFF_GA  = 4096;   // gates1 staging [128 r][8 b]
constexpr int OFF_GB  = 5120;   // gates2 staging
constexpr int OFF_BS1 = 6144;   // 128
constexpr int OFF_WX  = 6272;   // 128
constexpr int OFF_BS2 = 6400;   // 128
constexpr int OFF_WO  = 6528;   // 128
constexpr int OFF_X   = 6656;   // 8
constexpr int OFF_BO  = 6664;   // 1 (+pad)
constexpr int SM_FLOATS = 6668;
constexpr int SM_BYTES = SM_FLOATS * 4;  // ~26.7 KB

__device__ __forceinline__ uint32_t s2u(const void* p) {
    return (uint32_t)__cvta_generic_to_shared(p);
}
__device__ __forceinline__ float to_tf32(float x) {
    float r;
    asm("cvt.rna.tf32.f32 %0, %1;" : "=f"(r) : "f"(x));
    return r;
}
__device__ __forceinline__ uint32_t tfbits(float x) {
    return __float_as_uint(to_tf32(x));
}
__device__ __forceinline__ void mma8(float* d, const uint32_t* a, uint32_t b0,
                                     uint32_t b1) {
    asm volatile(
        "mma.sync.aligned.m16n8k8.row.col.f32.tf32.tf32.f32 "
        "{%0,%1,%2,%3}, {%4,%5,%6,%7}, {%8,%9}, {%0,%1,%2,%3};"
        : "+f"(d[0]), "+f"(d[1]), "+f"(d[2]), "+f"(d[3])
        : "r"(a[0]), "r"(a[1]), "r"(a[2]), "r"(a[3]), "r"(b0), "r"(b1));
}
__device__ __forceinline__ void st_remote(uint32_t laddr, uint32_t peer, float v) {
    uint32_t r;
    asm("mapa.shared::cluster.u32 %0, %1, %2;" : "=r"(r) : "r"(laddr), "r"(peer));
    asm volatile("st.shared::cluster.f32 [%0], %1;" ::"r"(r), "f"(v) : "memory");
}
__device__ __forceinline__ void cl_arrive() {
    asm volatile("barrier.cluster.arrive.aligned;" ::: "memory");
}
__device__ __forceinline__ void cl_wait() {
    asm volatile("barrier.cluster.wait.aligned;" ::: "memory");
}
__device__ __forceinline__ float sigf(float x) {
    return 1.0f / (1.0f + __expf(-x));
}
__device__ __forceinline__ float tanh_fast(float x) {
    return 2.0f / (1.0f + __expf(-2.0f * x)) - 1.0f;
}

__global__ void __launch_bounds__(NTH, 1) lstm_mma_kernel(
    const float* __restrict__ x, const float* __restrict__ Wih1,
    const float* __restrict__ Whh1, const float* __restrict__ bih1,
    const float* __restrict__ bhh1, const float* __restrict__ Wih2,
    const float* __restrict__ Whh2, const float* __restrict__ bih2,
    const float* __restrict__ bhh2, const float* __restrict__ Wout,
    const float* __restrict__ bout, float* __restrict__ out) {
    extern __shared__ float sm[];
    float* hT1 = sm + OFF_HT1;
    float* hT2 = sm + OFF_HT2;
    float* gbA = sm + OFF_GA;
    float* gbB = sm + OFF_GB;
    float* bs1s = sm + OFF_BS1;
    float* wxs = sm + OFF_WX;
    float* bs2s = sm + OFF_BS2;
    float* wos = sm + OFF_WO;
    float* xS = sm + OFF_X;
    float* boS = sm + OFF_BO;

    const int tid = threadIdx.x;
    const int lane = tid & 31;
    const int warp = tid >> 5;
    const int rank = blockIdx.x & 3;
    const int bbase = (blockIdx.x >> 2) * BC;
    const int U0 = rank * 32;

    // ---- per-thread MMA fragment coordinates ----
    const int q = lane & 3;          // k within 4
    const int g8 = lane >> 2;        // row group 0..7
    const int lr0 = warp * 16 + g8;  // local rows lr0, lr0+8
    const int lr1 = lr0 + 8;
    const int qg = q * 8 + g8;       // B-frag smem word offset (conflict-free)
    // global gate rows (r = gate*32 + unit; both lr in same gate block)
    const int G0 = ((lr0 >> 5) << 7) + U0 + (lr0 & 31);
    const int G1 = G0 + 8;

    // ---- weights -> registers as tf32 A-fragments ----
    uint32_t w1[64], w2h[64], w2i[64];
#pragma unroll
    for (int kt = 0; kt < 16; ++kt) {
        const int k0 = kt * 8 + q;
        w1[kt * 4 + 0] = tfbits(Whh1[G0 * Ht + k0]);
        w1[kt * 4 + 1] = tfbits(Whh1[G1 * Ht + k0]);
        w1[kt * 4 + 2] = tfbits(Whh1[G0 * Ht + k0 + 4]);
        w1[kt * 4 + 3] = tfbits(Whh1[G1 * Ht + k0 + 4]);
        w2h[kt * 4 + 0] = tfbits(Whh2[G0 * Ht + k0]);
        w2h[kt * 4 + 1] = tfbits(Whh2[G1 * Ht + k0]);
        w2h[kt * 4 + 2] = tfbits(Whh2[G0 * Ht + k0 + 4]);
        w2h[kt * 4 + 3] = tfbits(Whh2[G1 * Ht + k0 + 4]);
        w2i[kt * 4 + 0] = tfbits(Wih2[G0 * Ht + k0]);
        w2i[kt * 4 + 1] = tfbits(Wih2[G1 * Ht + k0]);
        w2i[kt * 4 + 2] = tfbits(Wih2[G0 * Ht + k0 + 4]);
        w2i[kt * 4 + 3] = tfbits(Wih2[G1 * Ht + k0 + 4]);
    }

    // ---- biases / small vectors into SMEM ----
    for (int r = tid; r < 128; r += NTH) {
        const int G = ((r >> 5) << 7) + U0 + (r & 31);
        bs1s[r] = bih1[G] + bhh1[G];
        wxs[r] = Wih1[G];
        bs2s[r] = bih2[G] + bhh2[G];
        wos[r] = Wout[r];
    }
    for (int i = tid; i < 4096; i += NTH) sm[OFF_HT1 + i] = 0.0f;  // hT1+hT2
    if (tid == 0) boS[0] = bout[0];
    __syncthreads();
    cl_arrive();
    cl_wait();  // peers' h buffers zeroed

    const uint32_t h1u = s2u(hT1);
    const uint32_t h2u = s2u(hT2);
    const uint32_t p1 = (rank + 1) & 3, p2r = (rank + 2) & 3, p3 = (rank + 3) & 3;
    const float boutr = boS[0];

    // epilogue mapping: bb = tid&7 (batch), uu = tid>>3 (unit 0..31)
    const int bb = tid & 7;
    const int uu = tid >> 3;
    const int hword = (U0 + uu) * 8 + bb;

    float c1 = 0.0f, c2 = 0.0f;
    float xreg = (tid < BC) ? x[(bbase + tid) * Tt + 0] : 0.0f;

    for (int t = 0; t < Tt; ++t) {
        const int p = t & 1;
        const int pp = p ^ 1;

        if (tid < BC) {
            xS[tid] = xreg;
            if (t + 1 < Tt) xreg = x[(bbase + tid) * Tt + (t + 1)];
        }

        // ===== stage 1: D1 = Whh1 @ h1(t-1); D2 = Whh2 @ h2(t-1) =====
        float d1a[4] = {0, 0, 0, 0}, d1b[4] = {0, 0, 0, 0};
        float d2a[4] = {0, 0, 0, 0}, d2b[4] = {0, 0, 0, 0};
        {
            const float* h1p = hT1 + pp * 1024;
            const float* h2p = hT2 + pp * 1024;
#pragma unroll
            for (int kt = 0; kt < 16; ++kt) {
                const uint32_t b0 = __float_as_uint(h1p[kt * 64 + qg]);
                const uint32_t b1 = __float_as_uint(h1p[kt * 64 + 32 + qg]);
                mma8((kt & 1) ? d1b : d1a, &w1[kt * 4], b0, b1);
                const uint32_t e0 = __float_as_uint(h2p[kt * 64 + qg]);
                const uint32_t e1 = __float_as_uint(h2p[kt * 64 + 32 + qg]);
                mma8((kt & 1) ? d2b : d2a, &w2h[kt * 4], e0, e1);
            }
        }
        // store D1 -> gbA[row][batch] (float2: cols 2q, 2q+1)
        {
            float2* gA2 = reinterpret_cast<float2*>(gbA);
            gA2[lr0 * 4 + q] = make_float2(d1a[0] + d1b[0], d1a[1] + d1b[1]);
            gA2[lr1 * 4 + q] = make_float2(d1a[2] + d1b[2], d1a[3] + d1b[3]);
        }
        __syncthreads();

        // ===== epilogue A: gates1 -> c1/h1, push h1 cluster-wide =====
        {
            const float xv = xS[bb];
            const float gi = gbA[(0 * 32 + uu) * 8 + bb] + bs1s[0 * 32 + uu] + xv * wxs[0 * 32 + uu];
            const float gf = gbA[(1 * 32 + uu) * 8 + bb] + bs1s[1 * 32 + uu] + xv * wxs[1 * 32 + uu];
            const float gg = gbA[(2 * 32 + uu) * 8 + bb] + bs1s[2 * 32 + uu] + xv * wxs[2 * 32 + uu];
            const float go = gbA[(3 * 32 + uu) * 8 + bb] + bs1s[3 * 32 + uu] + xv * wxs[3 * 32 + uu];
            c1 = sigf(gf) * c1 + sigf(gi) * tanh_fast(gg);
            const float h1v = to_tf32(sigf(go) * tanh_fast(c1));
            hT1[p * 1024 + hword] = h1v;
            const uint32_t la = h1u + (uint32_t)(p * 1024 + hword) * 4u;
            st_remote(la, p1, h1v);
            st_remote(la, p2r, h1v);
            st_remote(la, p3, h1v);
        }
        cl_arrive();
        cl_wait();  // full h1(t) visible in every CTA

        // ===== stage 2: D2 += Wih2 @ h1(t) =====
        {
            const float* h1c = hT1 + p * 1024;
#pragma unroll
            for (int kt = 0; kt < 16; ++kt) {
                const uint32_t b0 = __float_as_uint(h1c[kt * 64 + qg]);
                const uint32_t b1 = __float_as_uint(h1c[kt * 64 + 32 + qg]);
                mma8((kt & 1) ? d2b : d2a, &w2i[kt * 4], b0, b1);
            }
            float2* gB2 = reinterpret_cast<float2*>(gbB);
            gB2[lr0 * 4 + q] = make_float2(d2a[0] + d2b[0], d2a[1] + d2b[1]);
            gB2[lr1 * 4 + q] = make_float2(d2a[2] + d2b[2], d2a[3] + d2b[3]);
        }
        __syncthreads();

        // ===== epilogue B: gates2 -> c2/h2, push h2 cluster-wide =====
        {
            const float gi = gbB[(0 * 32 + uu) * 8 + bb] + bs2s[0 * 32 + uu];
            const float gf = gbB[(1 * 32 + uu) * 8 + bb] + bs2s[1 * 32 + uu];
            const float gg = gbB[(2 * 32 + uu) * 8 + bb] + bs2s[2 * 32 + uu];
            const float go = gbB[(3 * 32 + uu) * 8 + bb] + bs2s[3 * 32 + uu];
            c2 = sigf(gf) * c2 + sigf(gi) * tanh_fast(gg);
            const float h2v = to_tf32(sigf(go) * tanh_fast(c2));
            hT2[p * 1024 + hword] = h2v;
            const uint32_t la = h2u + (uint32_t)(p * 1024 + hword) * 4u;
            st_remote(la, p1, h2v);
            st_remote(la, p2r, h2v);
            st_remote(la, p3, h2v);
        }
        cl_arrive();
        cl_wait();  // full h2(t) visible in every CTA

        // ===== output(t): warps 6,7 emit batches rank*2 + {0,1} =====
        if (warp >= 6) {
            const int bl = rank * 2 + (warp - 6);
            const float* h2c = hT2 + p * 1024;
            float s = 0.0f;
#pragma unroll
            for (int j = 0; j < 4; ++j) {
                const int k = lane + 32 * j;
                s += h2c[k * 8 + bl] * wos[k];
            }
            s += __shfl_xor_sync(0xffffffffu, s, 16);
            s += __shfl_xor_sync(0xffffffffu, s, 8);
            s += __shfl_xor_sync(0xffffffffu, s, 4);
            s += __shfl_xor_sync(0xffffffffu, s, 2);
            s += __shfl_xor_sync(0xffffffffu, s, 1);
            if (lane == 0) out[(bbase + bl) * Tt + t] = s + boutr;
        }
    }
}

}  // namespace

extern "C" void kernel_launch(void* const* d_in, const int* in_sizes, int n_in,
                              void* d_out, int out_size) {
    (void)in_sizes;
    (void)n_in;
    (void)out_size;
    const float* x = (const float*)d_in[0];
    const float* Wih1 = (const float*)d_in[1];
    const float* Whh1 = (const float*)d_in[2];
    const float* bih1 = (const float*)d_in[3];
    const float* bhh1 = (const float*)d_in[4];
    const float* Wih2 = (const float*)d_in[5];
    const float* Whh2 = (const float*)d_in[6];
    const float* bih2 = (const float*)d_in[7];
    const float* bhh2 = (const float*)d_in[8];
    const float* Wout = (const float*)d_in[9];
    const float* bout = (const float*)d_in[10];
    float* out = (float*)d_out;

    cudaFuncSetAttribute(lstm_mma_kernel,
                         cudaFuncAttributeMaxDynamicSharedMemorySize, SM_BYTES);

    cudaLaunchConfig_t cfg = {};
    cfg.gridDim = dim3((Bt / BC) * CL, 1, 1);  // 128 CTAs = 32 clusters of 4
    cfg.blockDim = dim3(NTH, 1, 1);
    cfg.dynamicSmemBytes = SM_BYTES;
    cfg.stream = 0;
    cudaLaunchAttribute attrs[1];
    attrs[0].id = cudaLaunchAttributeClusterDimension;
    attrs[0].val.clusterDim.x = CL;
    attrs[0].val.clusterDim.y = 1;
    attrs[0].val.clusterDim.z = 1;
    cfg.attrs = attrs;
    cfg.numAttrs = 1;

    cudaLaunchKernelEx(&cfg, lstm_mma_kernel, x, Wih1, Whh1, bih1, bhh1, Wih2,
                       Whh2, bih2, bhh2, Wout, bout, out);
}